// round 7
// baseline (speedup 1.0000x reference)
#include <cuda_runtime.h>
#include <math.h>
#include <stdint.h>

#define S_LEN 2048
#define BATCH 2
#define EMB   1024
#define NH    16
#define HD    64
#define HID   512
#define MROWS (S_LEN*BATCH)   // 4096
#define HSZ   (BATCH*NH*S_LEN*HD)

// ---------------- scratch (static device globals; no allocation) ----------
__device__ float g_qkv[3*HSZ];               // q|k|v in (B,H,S,D), tf32-rounded
__device__ float g_ctx[MROWS*EMB];           // (S,B,E) tf32-rounded
__device__ float g_t1 [MROWS*HID];
__device__ float g_mcomb[NH*HID];
__device__ float g_cbias[NH];
__device__ float g_mask[BATCH*NH*S_LEN];
__device__ float g_qr [MROWS*EMB];           // tf32-rounded query
__device__ float g_wqkv[3*EMB*EMB];          // tf32-rounded q_w|k_w|v_w
__device__ float g_wo [EMB*EMB];             // tf32-rounded out_w

// =================== helpers ===============================================
__device__ __forceinline__ uint32_t f2tf(float x) {
    uint32_t r; asm("cvt.rna.tf32.f32 %0, %1;" : "=r"(r) : "f"(x)); return r;
}
__device__ __forceinline__ float rtf(float x) { return __uint_as_float(f2tf(x)); }
__device__ __forceinline__ uint32_t smem_u32(const void* p) {
    uint32_t a;
    asm("{ .reg .u64 t; cvta.to.shared.u64 t, %1; cvt.u32.u64 %0, t; }"
        : "=r"(a) : "l"(p));
    return a;
}
__device__ __forceinline__ void cp16(uint32_t saddr, const void* g) {
    asm volatile("cp.async.cg.shared.global [%0], [%1], 16;"
                 :: "r"(saddr), "l"(g) : "memory");
}
__device__ __forceinline__ void mma_tf32(float* d, const uint32_t* a, const uint32_t* b) {
    asm volatile(
        "mma.sync.aligned.m16n8k8.row.col.f32.tf32.tf32.f32 "
        "{%0,%1,%2,%3}, {%4,%5,%6,%7}, {%8,%9}, {%0,%1,%2,%3};"
        : "+f"(d[0]), "+f"(d[1]), "+f"(d[2]), "+f"(d[3])
        : "r"(a[0]), "r"(a[1]), "r"(a[2]), "r"(a[3]), "r"(b[0]), "r"(b[1]));
}

// ---------------- fused tf32 rounding of query + 4 weight matrices --------
#define NQ4 (MROWS*EMB/4)      // 1048576
#define NW4 (EMB*EMB/4)        // 262144 = 1<<18
__global__ void round_all(const float* __restrict__ q,
                          const float* __restrict__ wq,
                          const float* __restrict__ wk,
                          const float* __restrict__ wv,
                          const float* __restrict__ wo,
                          float* __restrict__ dq,
                          float* __restrict__ dwqkv,
                          float* __restrict__ dwo)
{
    const int i = blockIdx.x * blockDim.x + threadIdx.x;
    const float4* src; float4* dst; int off;
    if (i < NQ4) { src = (const float4*)q; dst = (float4*)dq; off = i; }
    else {
        const int j = i - NQ4;
        const int z = j >> 18;
        off = j & (NW4 - 1);
        if      (z == 0) { src = (const float4*)wq; dst = (float4*)dwqkv; }
        else if (z == 1) { src = (const float4*)wk; dst = (float4*)dwqkv + NW4; }
        else if (z == 2) { src = (const float4*)wv; dst = (float4*)dwqkv + 2*NW4; }
        else             { src = (const float4*)wo; dst = (float4*)dwo; }
    }
    float4 v = src[off];
    v.x = rtf(v.x); v.y = rtf(v.y); v.z = rtf(v.z); v.w = rtf(v.w);
    dst[off] = v;
}

// =================== cp.async pipelined tf32 GEMM core =====================
#define GEMM_BODY(Ag, Wg)                                                      \
    float acc[4][4][4];                                                        \
    _Pragma("unroll")                                                          \
    for (int i = 0; i < 4; i++)                                                \
        _Pragma("unroll")                                                      \
        for (int j = 0; j < 4; j++)                                            \
            _Pragma("unroll")                                                  \
            for (int f = 0; f < 4; f++) acc[i][j][f] = 0.f;                    \
    const int NC = K >> 5;                                                     \
    const int r0 = tid >> 3;                                                   \
    const int sg = tid & 7;                                                    \
    {                                                                          \
        const uint32_t ab = sbase, wb = sbase + 4608u * 4u;                    \
        _Pragma("unroll")                                                      \
        for (int i = 0; i < 4; i++) {                                          \
            const int row = r0 + i * 32;                                       \
            const uint32_t off = (uint32_t)(row * 36 + sg * 4) * 4u;           \
            cp16(ab + off, Ag + (size_t)row * K + sg * 4);                     \
            cp16(wb + off, Wg + (size_t)row * K + sg * 4);                     \
        }                                                                      \
        asm volatile("cp.async.commit_group;" ::: "memory");                   \
    }                                                                          \
    for (int c = 0; c < NC; c++) {                                             \
        if (c + 1 < NC) {                                                      \
            const uint32_t st = (uint32_t)((c + 1) & 1) * 9216u * 4u;          \
            const uint32_t ab = sbase + st, wb = sbase + st + 4608u * 4u;      \
            const int kn = (c + 1) << 5;                                       \
            _Pragma("unroll")                                                  \
            for (int i = 0; i < 4; i++) {                                      \
                const int row = r0 + i * 32;                                   \
                const uint32_t off = (uint32_t)(row * 36 + sg * 4) * 4u;       \
                cp16(ab + off, Ag + (size_t)row * K + kn + sg * 4);            \
                cp16(wb + off, Wg + (size_t)row * K + kn + sg * 4);            \
            }                                                                  \
            asm volatile("cp.async.commit_group;" ::: "memory");               \
            asm volatile("cp.async.wait_group 1;" ::: "memory");               \
        } else {                                                               \
            asm volatile("cp.async.wait_group 0;" ::: "memory");               \
        }                                                                      \
        __syncthreads();                                                       \
        const uint32_t* As = sw + (c & 1) * 9216;                              \
        const uint32_t* Ws = As + 4608;                                        \
        _Pragma("unroll")                                                      \
        for (int ks = 0; ks < 4; ks++) {                                       \
            const int k0 = ks * 8;                                             \
            uint32_t af[4][4];                                                 \
            _Pragma("unroll")                                                  \
            for (int mt = 0; mt < 4; mt++) {                                   \
                const int r = wm * 64 + mt * 16 + gid;                         \
                af[mt][0] = As[ r      * 36 + k0 + tig    ];                   \
                af[mt][1] = As[(r + 8) * 36 + k0 + tig    ];                   \
                af[mt][2] = As[ r      * 36 + k0 + tig + 4];                   \
                af[mt][3] = As[(r + 8) * 36 + k0 + tig + 4];                   \
            }                                                                  \
            uint32_t bf[4][2];                                                 \
            _Pragma("unroll")                                                  \
            for (int nt = 0; nt < 4; nt++) {                                   \
                const int n = wn * 32 + nt * 8 + gid;                          \
                bf[nt][0] = Ws[n * 36 + k0 + tig    ];                         \
                bf[nt][1] = Ws[n * 36 + k0 + tig + 4];                         \
            }                                                                  \
            _Pragma("unroll")                                                  \
            for (int mt = 0; mt < 4; mt++)                                     \
                _Pragma("unroll")                                              \
                for (int nt = 0; nt < 4; nt++)                                 \
                    mma_tf32(acc[mt][nt], af[mt], bf[nt]);                     \
        }                                                                      \
        __syncthreads();                                                       \
    }

// ---- fused QKV projection ------------------------------------------------
__global__ __launch_bounds__(256, 2)
void mgemm_qkv(const float* __restrict__ A, const float* __restrict__ Wall,
               const float* __restrict__ bq, const float* __restrict__ bk,
               const float* __restrict__ bv, float* __restrict__ Call, int K)
{
    extern __shared__ uint32_t sw[];
    const uint32_t sbase = smem_u32(sw);
    const int tid  = threadIdx.x;
    const int wid  = tid >> 5;
    const int lane = tid & 31;
    const int gid  = lane >> 2;
    const int tig  = lane & 3;
    const int wm   = wid >> 2;
    const int wn   = wid & 3;
    const int z    = blockIdx.z;

    const float* Ag = A + (size_t)blockIdx.y * 128 * K;
    const float* Wg = Wall + (size_t)z * EMB * EMB + (size_t)blockIdx.x * 128 * K;
    const float* bias = (z == 0) ? bq : (z == 1) ? bk : bv;
    float* C = Call + (size_t)z * HSZ;
    const float scale = (z == 0) ? 0.125f : 1.f;

    GEMM_BODY(Ag, Wg)

    #pragma unroll
    for (int mt = 0; mt < 4; mt++) {
        #pragma unroll
        for (int nt = 0; nt < 4; nt++) {
            const int n = blockIdx.x * 128 + wn * 32 + nt * 8 + tig * 2;
            const float b0 = bias[n], b1 = bias[n + 1];
            #pragma unroll
            for (int half = 0; half < 2; half++) {
                const int m = blockIdx.y * 128 + wm * 64 + mt * 16 + gid + half * 8;
                float2 v;
                v.x = rtf((acc[mt][nt][half * 2 + 0] + b0) * scale);
                v.y = rtf((acc[mt][nt][half * 2 + 1] + b1) * scale);
                const int s = m >> 1, b = m & 1;
                const int h = n >> 6, d = n & 63;
                *(float2*)(C + (((size_t)(b * NH + h)) * S_LEN + s) * HD + d) = v;
            }
        }
    }
}

// ---- output projection ----------------------------------------------------
__global__ __launch_bounds__(256, 2)
void mgemm_out(const float* __restrict__ A, const float* __restrict__ W,
               const float* __restrict__ bias, float* __restrict__ C, int K)
{
    extern __shared__ uint32_t sw[];
    const uint32_t sbase = smem_u32(sw);
    const int tid  = threadIdx.x;
    const int wid  = tid >> 5;
    const int lane = tid & 31;
    const int gid  = lane >> 2;
    const int tig  = lane & 3;
    const int wm   = wid >> 2;
    const int wn   = wid & 3;

    const float* Ag = A + (size_t)blockIdx.y * 128 * K;
    const float* Wg = W + (size_t)blockIdx.x * 128 * K;

    GEMM_BODY(Ag, Wg)

    #pragma unroll
    for (int mt = 0; mt < 4; mt++) {
        #pragma unroll
        for (int nt = 0; nt < 4; nt++) {
            const int n = blockIdx.x * 128 + wn * 32 + nt * 8 + tig * 2;
            const float b0 = bias[n], b1 = bias[n + 1];
            #pragma unroll
            for (int half = 0; half < 2; half++) {
                const int m = blockIdx.y * 128 + wm * 64 + mt * 16 + gid + half * 8;
                float2 v;
                v.x = acc[mt][nt][half * 2 + 0] + b0;
                v.y = acc[mt][nt][half * 2 + 1] + b1;
                *(float2*)(C + (size_t)m * (gridDim.x * 128) + n) = v;
            }
        }
    }
}

// =================== split-tf32 (3xMMA) GEMM + ReLU for the mask MLP =======
__global__ __launch_bounds__(256)
void mgemm_3x_relu(const float* __restrict__ A, const float* __restrict__ W,
                   const float* __restrict__ bias, float* __restrict__ C, int K)
{
    extern __shared__ uint32_t sw[];
    const uint32_t sbase = smem_u32(sw);
    const float* swf = (const float*)sw;
    const int tid  = threadIdx.x;
    const int wid  = tid >> 5;
    const int lane = tid & 31;
    const int gid  = lane >> 2;
    const int tig  = lane & 3;
    const int wm   = wid >> 2;
    const int wn   = wid & 3;

    const float* Ag = A + (size_t)blockIdx.y * 128 * K;
    const float* Wg = W + (size_t)blockIdx.x * 128 * K;

    float acc[4][4][4];
    #pragma unroll
    for (int i = 0; i < 4; i++)
        #pragma unroll
        for (int j = 0; j < 4; j++)
            #pragma unroll
            for (int f = 0; f < 4; f++) acc[i][j][f] = 0.f;

    const int NC = K >> 5;
    const int r0 = tid >> 3;
    const int sg = tid & 7;

    {
        const uint32_t ab = sbase, wb = sbase + 4608u * 4u;
        #pragma unroll
        for (int i = 0; i < 4; i++) {
            const int row = r0 + i * 32;
            const uint32_t off = (uint32_t)(row * 36 + sg * 4) * 4u;
            cp16(ab + off, Ag + (size_t)row * K + sg * 4);
            cp16(wb + off, Wg + (size_t)row * K + sg * 4);
        }
        asm volatile("cp.async.commit_group;" ::: "memory");
    }

    for (int c = 0; c < NC; c++) {
        if (c + 1 < NC) {
            const uint32_t st = (uint32_t)((c + 1) & 1) * 9216u * 4u;
            const uint32_t ab = sbase + st, wb = sbase + st + 4608u * 4u;
            const int kn = (c + 1) << 5;
            #pragma unroll
            for (int i = 0; i < 4; i++) {
                const int row = r0 + i * 32;
                const uint32_t off = (uint32_t)(row * 36 + sg * 4) * 4u;
                cp16(ab + off, Ag + (size_t)row * K + kn + sg * 4);
                cp16(wb + off, Wg + (size_t)row * K + kn + sg * 4);
            }
            asm volatile("cp.async.commit_group;" ::: "memory");
            asm volatile("cp.async.wait_group 1;" ::: "memory");
        } else {
            asm volatile("cp.async.wait_group 0;" ::: "memory");
        }
        __syncthreads();

        const float* As = swf + (c & 1) * 9216;
        const float* Ws = As + 4608;
        #pragma unroll
        for (int ks = 0; ks < 4; ks++) {
            const int k0 = ks * 8;
            uint32_t ah[4][4], al[4][4];
            #pragma unroll
            for (int mt = 0; mt < 4; mt++) {
                const int r = wm * 64 + mt * 16 + gid;
                float a0 = As[ r      * 36 + k0 + tig    ];
                float a1 = As[(r + 8) * 36 + k0 + tig    ];
                float a2 = As[ r      * 36 + k0 + tig + 4];
                float a3 = As[(r + 8) * 36 + k0 + tig + 4];
                ah[mt][0] = f2tf(a0); al[mt][0] = f2tf(a0 - __uint_as_float(ah[mt][0]));
                ah[mt][1] = f2tf(a1); al[mt][1] = f2tf(a1 - __uint_as_float(ah[mt][1]));
                ah[mt][2] = f2tf(a2); al[mt][2] = f2tf(a2 - __uint_as_float(ah[mt][2]));
                ah[mt][3] = f2tf(a3); al[mt][3] = f2tf(a3 - __uint_as_float(ah[mt][3]));
            }
            uint32_t bh_[4][2], bl_[4][2];
            #pragma unroll
            for (int nt = 0; nt < 4; nt++) {
                const int n = wn * 32 + nt * 8 + gid;
                float b0 = Ws[n * 36 + k0 + tig    ];
                float b1 = Ws[n * 36 + k0 + tig + 4];
                bh_[nt][0] = f2tf(b0); bl_[nt][0] = f2tf(b0 - __uint_as_float(bh_[nt][0]));
                bh_[nt][1] = f2tf(b1); bl_[nt][1] = f2tf(b1 - __uint_as_float(bh_[nt][1]));
            }
            #pragma unroll
            for (int mt = 0; mt < 4; mt++)
                #pragma unroll
                for (int nt = 0; nt < 4; nt++) {
                    mma_tf32(acc[mt][nt], al[mt], bh_[nt]);
                    mma_tf32(acc[mt][nt], ah[mt], bl_[nt]);
                    mma_tf32(acc[mt][nt], ah[mt], bh_[nt]);
                }
        }
        __syncthreads();
    }

    #pragma unroll
    for (int mt = 0; mt < 4; mt++) {
        #pragma unroll
        for (int nt = 0; nt < 4; nt++) {
            const int n = blockIdx.x * 128 + wn * 32 + nt * 8 + tig * 2;
            const float b0 = bias[n], b1 = bias[n + 1];
            #pragma unroll
            for (int half = 0; half < 2; half++) {
                const int m = blockIdx.y * 128 + wm * 64 + mt * 16 + gid + half * 8;
                float2 v;
                v.x = fmaxf(acc[mt][nt][half * 2 + 0] + b0, 0.f);
                v.y = fmaxf(acc[mt][nt][half * 2 + 1] + b1, 0.f);
                *(float2*)(C + (size_t)m * (gridDim.x * 128) + n) = v;
            }
        }
    }
}

// =================== tensor-core flash attention (512 thr, 256 Q rows) =====
// 16 warps (4/SMSP), warp w owns Q rows [w*16, w*16+16). 3-stage K/V ring.
// smem: 3 x (K 4352 + V 4352 words) = 104448 B. P converted in-place in sa.
__global__ __launch_bounds__(512)
void flash_tc(const float* __restrict__ Q, const float* __restrict__ Kg,
              const float* __restrict__ Vg, const float* __restrict__ gate,
              float* __restrict__ ctx)
{
    extern __shared__ uint32_t sw[];
    const uint32_t sbase = smem_u32(sw);
    const int tid  = threadIdx.x;
    const int wid  = tid >> 5;
    const int lane = tid & 31;
    const int gid  = lane >> 2;
    const int tig  = lane & 3;
    const int bh   = blockIdx.y;
    const int b    = bh >> 4, h = bh & 15;
    const int q0   = blockIdx.x * 256;

    const float* Qt = Q  + ((size_t)bh * S_LEN + q0) * HD;
    const float* Kb = Kg + (size_t)bh * S_LEN * HD;
    const float* Vb = Vg + (size_t)bh * S_LEN * HD;

    // ---- stage Q in two 128-row chunks via stage-0 smem --------------------
    uint32_t qa[8][4];
    #pragma unroll 1
    for (int halfq = 0; halfq < 2; halfq++) {
        #pragma unroll
        for (int i = 0; i < 4; i++) {
            const int fi = tid + i * 512;           // 0..2047 float4s
            const int r = fi >> 4, c4 = (fi & 15) * 4;
            float4 v = *(const float4*)(Qt + (halfq * 128 + r) * 64 + c4);
            uint32_t* d = &sw[r * 68 + c4];
            d[0] = __float_as_uint(v.x); d[1] = __float_as_uint(v.y);
            d[2] = __float_as_uint(v.z); d[3] = __float_as_uint(v.w);
        }
        __syncthreads();
        if ((wid >> 3) == halfq) {
            const int r0 = (wid & 7) * 16 + gid;
            #pragma unroll
            for (int ks = 0; ks < 8; ks++) {
                qa[ks][0] = sw[ r0      * 68 + ks * 8 + tig    ];
                qa[ks][1] = sw[(r0 + 8) * 68 + ks * 8 + tig    ];
                qa[ks][2] = sw[ r0      * 68 + ks * 8 + tig + 4];
                qa[ks][3] = sw[(r0 + 8) * 68 + ks * 8 + tig + 4];
            }
        }
        __syncthreads();
    }

    // ---- issue first two K/V tiles into stages 0,1 -------------------------
    #pragma unroll 1
    for (int t = 0; t < 2; t++) {
        const uint32_t kb = sbase + (uint32_t)t * 8704u * 4u;
        const uint32_t vb = kb + 4352u * 4u;
        const float* Ksrc = Kb + (size_t)t * 64 * 64;
        const float* Vsrc = Vb + (size_t)t * 64 * 64;
        #pragma unroll
        for (int i = 0; i < 2; i++) {
            const int fi = tid + i * 512;        // 0..1023
            const int r = fi >> 4, c4 = (fi & 15) * 4;
            cp16(kb + (uint32_t)(r * 68 + c4) * 4u, Ksrc + r * 64 + c4);
            cp16(vb + (uint32_t)(r * 68 + c4) * 4u, Vsrc + r * 64 + c4);
        }
        asm volatile("cp.async.commit_group;" ::: "memory");
    }

    float miA = -INFINITY, miB = -INFINITY, liA = 0.f, liB = 0.f;
    float oa[8][4];
    #pragma unroll
    for (int nt = 0; nt < 8; nt++)
        #pragma unroll
        for (int f = 0; f < 4; f++) oa[nt][f] = 0.f;

    const int NT = S_LEN / 64;
    int stage = 0, pstage = 2;
    for (int t = 0; t < NT; t++) {
        if (t + 2 < NT) {
            const uint32_t kb = sbase + (uint32_t)pstage * 8704u * 4u;
            const uint32_t vb = kb + 4352u * 4u;
            const float* Ksrc = Kb + (size_t)(t + 2) * 64 * 64;
            const float* Vsrc = Vb + (size_t)(t + 2) * 64 * 64;
            #pragma unroll
            for (int i = 0; i < 2; i++) {
                const int fi = tid + i * 512;
                const int r = fi >> 4, c4 = (fi & 15) * 4;
                cp16(kb + (uint32_t)(r * 68 + c4) * 4u, Ksrc + r * 64 + c4);
                cp16(vb + (uint32_t)(r * 68 + c4) * 4u, Vsrc + r * 64 + c4);
            }
            asm volatile("cp.async.commit_group;" ::: "memory");
            asm volatile("cp.async.wait_group 2;" ::: "memory");
        } else if (t + 1 < NT) {
            asm volatile("cp.async.wait_group 1;" ::: "memory");
        } else {
            asm volatile("cp.async.wait_group 0;" ::: "memory");
        }
        __syncthreads();
        const uint32_t* Ks = sw + stage * 8704;
        const uint32_t* Vs = Ks + 4352;

        // ---- S = Q K^T (warp tile 16x64) -----------------------------------
        float sa[8][4];
        #pragma unroll
        for (int nt = 0; nt < 8; nt++)
            #pragma unroll
            for (int f = 0; f < 4; f++) sa[nt][f] = 0.f;
        #pragma unroll
        for (int ks = 0; ks < 8; ks++) {
            #pragma unroll
            for (int nt = 0; nt < 8; nt++) {
                uint32_t bf[2];
                bf[0] = Ks[(nt * 8 + gid) * 68 + ks * 8 + tig    ];
                bf[1] = Ks[(nt * 8 + gid) * 68 + ks * 8 + tig + 4];
                mma_tf32(sa[nt], qa[ks], bf);
            }
        }

        // ---- online softmax; P converted to tf32 IN PLACE in sa ------------
        float rmA = -INFINITY, rmB = -INFINITY;
        #pragma unroll
        for (int nt = 0; nt < 8; nt++) {
            rmA = fmaxf(rmA, fmaxf(sa[nt][0], sa[nt][1]));
            rmB = fmaxf(rmB, fmaxf(sa[nt][2], sa[nt][3]));
        }
        rmA = fmaxf(rmA, __shfl_xor_sync(0xffffffffu, rmA, 1));
        rmA = fmaxf(rmA, __shfl_xor_sync(0xffffffffu, rmA, 2));
        rmB = fmaxf(rmB, __shfl_xor_sync(0xffffffffu, rmB, 1));
        rmB = fmaxf(rmB, __shfl_xor_sync(0xffffffffu, rmB, 2));

        const float mAn = fmaxf(miA, rmA);
        const float mBn = fmaxf(miB, rmB);
        const float aA  = __expf(miA - mAn);
        const float aB  = __expf(miB - mBn);
        miA = mAn; miB = mBn;

        float rsA = 0.f, rsB = 0.f;
        #pragma unroll
        for (int nt = 0; nt < 8; nt++) {
            const float p0 = __expf(sa[nt][0] - mAn);
            const float p1 = __expf(sa[nt][1] - mAn);
            const float p2 = __expf(sa[nt][2] - mBn);
            const float p3 = __expf(sa[nt][3] - mBn);
            rsA += p0 + p1; rsB += p2 + p3;
            sa[nt][0] = __uint_as_float(f2tf(p0));
            sa[nt][1] = __uint_as_float(f2tf(p1));
            sa[nt][2] = __uint_as_float(f2tf(p2));
            sa[nt][3] = __uint_as_float(f2tf(p3));
        }
        rsA += __shfl_xor_sync(0xffffffffu, rsA, 1);
        rsA += __shfl_xor_sync(0xffffffffu, rsA, 2);
        rsB += __shfl_xor_sync(0xffffffffu, rsB, 1);
        rsB += __shfl_xor_sync(0xffffffffu, rsB, 2);
        liA = liA * aA + rsA;
        liB = liB * aB + rsB;
        #pragma unroll
        for (int nt = 0; nt < 8; nt++) {
            oa[nt][0] *= aA; oa[nt][1] *= aA;
            oa[nt][2] *= aB; oa[nt][3] *= aB;
        }

        // ---- O += P V (P remapped to A-fragments via quad shfl) ------------
        const int srcA = (lane & ~3) | (tig >> 1);
        const int srcB = srcA + 2;
        #pragma unroll
        for (int ks = 0; ks < 8; ks++) {
            const uint32_t p0 = __float_as_uint(sa[ks][0]);
            const uint32_t p1 = __float_as_uint(sa[ks][1]);
            const uint32_t p2 = __float_as_uint(sa[ks][2]);
            const uint32_t p3 = __float_as_uint(sa[ks][3]);
            const uint32_t v00 = __shfl_sync(0xffffffffu, p0, srcA);
            const uint32_t v01 = __shfl_sync(0xffffffffu, p1, srcA);
            const uint32_t v10 = __shfl_sync(0xffffffffu, p2, srcA);
            const uint32_t v11 = __shfl_sync(0xffffffffu, p3, srcA);
            const uint32_t v20 = __shfl_sync(0xffffffffu, p0, srcB);
            const uint32_t v21 = __shfl_sync(0xffffffffu, p1, srcB);
            const uint32_t v30 = __shfl_sync(0xffffffffu, p2, srcB);
            const uint32_t v31 = __shfl_sync(0xffffffffu, p3, srcB);
            uint32_t af[4];
            af[0] = (tig & 1) ? v01 : v00;
            af[1] = (tig & 1) ? v11 : v10;
            af[2] = (tig & 1) ? v21 : v20;
            af[3] = (tig & 1) ? v31 : v30;
            #pragma unroll
            for (int nt = 0; nt < 8; nt++) {
                uint32_t bf[2];
                bf[0] = Vs[(ks * 8 + tig    ) * 68 + nt * 8 + gid];
                bf[1] = Vs[(ks * 8 + tig + 4) * 68 + nt * 8 + gid];
                mma_tf32(oa[nt], af, bf);
            }
        }
        __syncthreads();

        stage  = (stage  == 2) ? 0 : stage  + 1;
        pstage = (pstage == 2) ? 0 : pstage + 1;
    }

    const int sA = q0 + wid * 16 + gid;
    const int sB = sA + 8;
    const float gA = gate[(size_t)bh * S_LEN + sA];
    const float gB = gate[(size_t)bh * S_LEN + sB];
    const float invA = gA / liA;
    const float invB = gB / liB;
    #pragma unroll
    for (int nt = 0; nt < 8; nt++) {
        const int col = h * 64 + nt * 8 + tig * 2;
        float2 va = { rtf(oa[nt][0] * invA), rtf(oa[nt][1] * invA) };
        float2 vb = { rtf(oa[nt][2] * invB), rtf(oa[nt][3] * invB) };
        *(float2*)(ctx + ((size_t)sA * BATCH + b) * EMB + col) = va;
        *(float2*)(ctx + ((size_t)sB * BATCH + b) * EMB + col) = vb;
    }
}

// ---------------- fold head_sig into inf2 ---------------------------------
__global__ void combine_sig(const float* __restrict__ hs,
                            const float* __restrict__ w2,
                            const float* __restrict__ b2,
                            float* __restrict__ mcomb,
                            float* __restrict__ cbias)
{
    const int idx = blockIdx.x * blockDim.x + threadIdx.x;
    if (idx < NH * HID) {
        const int h = idx / HID, k = idx % HID;
        float a = 0.f;
        #pragma unroll
        for (int j = 0; j < 64; j++) a += hs[h*64 + j] * w2[j*HID + k];
        mcomb[idx] = a;
    }
    if (idx < NH) {
        float a = 0.f;
        #pragma unroll
        for (int j = 0; j < 64; j++) a += hs[idx*64 + j] * b2[j];
        cbias[idx] = a;
    }
}

// ---------------- head scores + top-12 mask (smem-cached mcomb) -----------
// block = 256 threads = 8 warps x 4 rows = 32 rows; grid = 128.
__global__ __launch_bounds__(256)
void head_scores(const float* __restrict__ t1, const float* __restrict__ mcomb,
                 const float* __restrict__ cbias, float* __restrict__ mask)
{
    __shared__ float smc[NH * HID];     // 32 KB
    const int tid  = threadIdx.x;
    const int lane = tid & 31;
    const int w    = tid >> 5;
    for (int i = tid; i < NH * HID; i += 256) smc[i] = mcomb[i];
    __syncthreads();

    #pragma unroll 1
    for (int rr = 0; rr < 4; rr++) {
        const int rowi = blockIdx.x * 32 + w * 4 + rr;
        const float* row = t1 + (size_t)rowi * HID;

        float acc[NH];
        #pragma unroll
        for (int h = 0; h < NH; h++) acc[h] = 0.f;
        for (int k = lane; k < HID; k += 32) {
            const float a = row[k];
            #pragma unroll
            for (int h = 0; h < NH; h++) acc[h] += a * smc[h * HID + k];
        }
        #pragma unroll
        for (int h = 0; h < NH; h++)
            #pragma unroll
            for (int off = 16; off > 0; off >>= 1)
                acc[h] += __shfl_xor_sync(0xffffffffu, acc[h], off);

        if (lane == 0) {
            float sc[NH], tmp[NH];
            #pragma unroll
            for (int h = 0; h < NH; h++) { sc[h] = acc[h] + cbias[h]; tmp[h] = sc[h]; }
            float thr = 0.f;
            for (int it = 0; it < NH - 4; it++) {
                int bi = 0; float bv = tmp[0];
                #pragma unroll
                for (int h = 1; h < NH; h++) if (tmp[h] > bv) { bv = tmp[h]; bi = h; }
                thr = bv; tmp[bi] = -INFINITY;
            }
            const int s = rowi >> 1, b = rowi & 1;
            #pragma unroll
            for (int h = 0; h < NH; h++)
                mask[((size_t)(b * NH + h)) * S_LEN + s] = (sc[h] >= thr) ? 1.f : 0.f;
        }
    }
}

// ---------------------------------------------------------------------------
extern "C" void kernel_launch(void* const* d_in, const int* in_sizes, int n_in,
                              void* d_out, int out_size)
{
    const float* query   = (const float*)d_in[0];
    const float* q_w     = (const float*)d_in[1];
    const float* q_b     = (const float*)d_in[2];
    const float* k_w     = (const float*)d_in[3];
    const float* k_b     = (const float*)d_in[4];
    const float* v_w     = (const float*)d_in[5];
    const float* v_b     = (const float*)d_in[6];
    const float* out_w   = (const float*)d_in[7];
    const float* out_b   = (const float*)d_in[8];
    const float* inf1_w  = (const float*)d_in[9];
    const float* inf1_b  = (const float*)d_in[10];
    const float* inf2_w  = (const float*)d_in[11];
    const float* inf2_b  = (const float*)d_in[12];
    const float* head_sig= (const float*)d_in[13];
    float* out = (float*)d_out;

    float *pqkv, *pctx, *pt1, *pmc, *pcb, *pmask, *pqr, *pwqkv, *pwo;
    cudaGetSymbolAddress((void**)&pqkv, g_qkv);
    cudaGetSymbolAddress((void**)&pctx, g_ctx);
    cudaGetSymbolAddress((void**)&pt1,  g_t1);
    cudaGetSymbolAddress((void**)&pmc,  g_mcomb);
    cudaGetSymbolAddress((void**)&pcb,  g_cbias);
    cudaGetSymbolAddress((void**)&pmask,g_mask);
    cudaGetSymbolAddress((void**)&pqr,  g_qr);
    cudaGetSymbolAddress((void**)&pwqkv,g_wqkv);
    cudaGetSymbolAddress((void**)&pwo,  g_wo);

    const int GS = 73728;
    cudaFuncSetAttribute(mgemm_qkv, cudaFuncAttributeMaxDynamicSharedMemorySize, GS);
    cudaFuncSetAttribute(mgemm_out, cudaFuncAttributeMaxDynamicSharedMemorySize, GS);
    cudaFuncSetAttribute(mgemm_3x_relu, cudaFuncAttributeMaxDynamicSharedMemorySize, GS);

    // 0) pre-round query + all 4 big weight matrices in ONE launch
    {
        const int total = NQ4 + 4 * NW4;
        round_all<<<(total + 255)/256, 256>>>(query, q_w, k_w, v_w, out_w,
                                              pqr, pwqkv, pwo);
    }

    // 1) fold head_sig into inf2
    combine_sig<<<(NH*HID + 255)/256, 256>>>(head_sig, inf2_w, inf2_b, pmc, pcb);

    // 2) mask MLP: split-tf32 (near-fp32) for top-k stability
    {
        dim3 g(HID/128, MROWS/128);
        mgemm_3x_relu<<<g, 256, GS>>>(query, inf1_w, inf1_b, pt1, EMB);
    }

    // 3) head scores + top-12 mask (32 rows/block)
    head_scores<<<MROWS/32, 256>>>(pt1, pmc, pcb, pmask);

    // 4) fused Q,K,V projections -> (B,H,S,D), one launch (grid.z = 3)
    {
        dim3 g(EMB/128, MROWS/128, 3);
        mgemm_qkv<<<g, 256, GS>>>(pqr, pwqkv, q_b, k_b, v_b, pqkv, EMB);
    }

    // 5) flash attention: 512 threads, 256 Q rows/CTA, 3-stage ring
    {
        const int smem = 26112 * (int)sizeof(uint32_t);   // 104448 B
        cudaFuncSetAttribute(flash_tc,
                             cudaFuncAttributeMaxDynamicSharedMemorySize, smem);
        dim3 g(S_LEN/256, BATCH*NH);
        flash_tc<<<g, 512, smem>>>(pqkv, pqkv + HSZ, pqkv + 2*HSZ, pmask, pctx);
    }

    // 6) output projection
    {
        dim3 g(EMB/128, MROWS/128);
        mgemm_out<<<g, 256, GS>>>(pctx, pwo, out_b, out, EMB);
    }
    (void)in_sizes; (void)n_in; (void)out_size;
}

// round 8
// speedup vs baseline: 1.1441x; 1.1441x over previous
#include <cuda_runtime.h>
#include <math.h>
#include <stdint.h>

#define S_LEN 2048
#define BATCH 2
#define EMB   1024
#define NH    16
#define HD    64
#define HID   512
#define MROWS (S_LEN*BATCH)   // 4096
#define HSZ   (BATCH*NH*S_LEN*HD)

// ---------------- scratch (static device globals; no allocation) ----------
__device__ float g_qkv[3*HSZ];               // q|k|v in (B,H,S,D), tf32-rounded
__device__ float g_ctx[MROWS*EMB];           // (S,B,E) tf32-rounded
__device__ float g_t1 [MROWS*HID];
__device__ float g_mcomb[NH*HID];
__device__ float g_cbias[NH];
__device__ float g_mask[BATCH*NH*S_LEN];
__device__ float g_qr [MROWS*EMB];           // tf32-rounded query
__device__ float g_wqkv[3*EMB*EMB];          // tf32-rounded q_w|k_w|v_w
__device__ float g_wo [EMB*EMB];             // tf32-rounded out_w

// =================== helpers ===============================================
__device__ __forceinline__ uint32_t f2tf(float x) {
    uint32_t r; asm("cvt.rna.tf32.f32 %0, %1;" : "=r"(r) : "f"(x)); return r;
}
__device__ __forceinline__ float rtf(float x) { return __uint_as_float(f2tf(x)); }
__device__ __forceinline__ uint32_t smem_u32(const void* p) {
    uint32_t a;
    asm("{ .reg .u64 t; cvta.to.shared.u64 t, %1; cvt.u32.u64 %0, t; }"
        : "=r"(a) : "l"(p));
    return a;
}
__device__ __forceinline__ void cp16(uint32_t saddr, const void* g) {
    asm volatile("cp.async.cg.shared.global [%0], [%1], 16;"
                 :: "r"(saddr), "l"(g) : "memory");
}
__device__ __forceinline__ void mma_tf32(float* d, const uint32_t* a, const uint32_t* b) {
    asm volatile(
        "mma.sync.aligned.m16n8k8.row.col.f32.tf32.tf32.f32 "
        "{%0,%1,%2,%3}, {%4,%5,%6,%7}, {%8,%9}, {%0,%1,%2,%3};"
        : "+f"(d[0]), "+f"(d[1]), "+f"(d[2]), "+f"(d[3])
        : "r"(a[0]), "r"(a[1]), "r"(a[2]), "r"(a[3]), "r"(b[0]), "r"(b[1]));
}

// ---------------- fused tf32 rounding of query + 4 weight matrices --------
#define NQ4 (MROWS*EMB/4)      // 1048576
#define NW4 (EMB*EMB/4)        // 262144 = 1<<18
__global__ void round_all(const float* __restrict__ q,
                          const float* __restrict__ wq,
                          const float* __restrict__ wk,
                          const float* __restrict__ wv,
                          const float* __restrict__ wo,
                          float* __restrict__ dq,
                          float* __restrict__ dwqkv,
                          float* __restrict__ dwo)
{
    const int i = blockIdx.x * blockDim.x + threadIdx.x;
    const float4* src; float4* dst; int off;
    if (i < NQ4) { src = (const float4*)q; dst = (float4*)dq; off = i; }
    else {
        const int j = i - NQ4;
        const int z = j >> 18;
        off = j & (NW4 - 1);
        if      (z == 0) { src = (const float4*)wq; dst = (float4*)dwqkv; }
        else if (z == 1) { src = (const float4*)wk; dst = (float4*)dwqkv + NW4; }
        else if (z == 2) { src = (const float4*)wv; dst = (float4*)dwqkv + 2*NW4; }
        else             { src = (const float4*)wo; dst = (float4*)dwo; }
    }
    float4 v = src[off];
    v.x = rtf(v.x); v.y = rtf(v.y); v.z = rtf(v.z); v.w = rtf(v.w);
    dst[off] = v;
}

// =================== cp.async pipelined tf32 GEMM core =====================
#define GEMM_BODY(Ag, Wg)                                                      \
    float acc[4][4][4];                                                        \
    _Pragma("unroll")                                                          \
    for (int i = 0; i < 4; i++)                                                \
        _Pragma("unroll")                                                      \
        for (int j = 0; j < 4; j++)                                            \
            _Pragma("unroll")                                                  \
            for (int f = 0; f < 4; f++) acc[i][j][f] = 0.f;                    \
    const int NC = K >> 5;                                                     \
    const int r0 = tid >> 3;                                                   \
    const int sg = tid & 7;                                                    \
    {                                                                          \
        const uint32_t ab = sbase, wb = sbase + 4608u * 4u;                    \
        _Pragma("unroll")                                                      \
        for (int i = 0; i < 4; i++) {                                          \
            const int row = r0 + i * 32;                                       \
            const uint32_t off = (uint32_t)(row * 36 + sg * 4) * 4u;           \
            cp16(ab + off, Ag + (size_t)row * K + sg * 4);                     \
            cp16(wb + off, Wg + (size_t)row * K + sg * 4);                     \
        }                                                                      \
        asm volatile("cp.async.commit_group;" ::: "memory");                   \
    }                                                                          \
    for (int c = 0; c < NC; c++) {                                             \
        if (c + 1 < NC) {                                                      \
            const uint32_t st = (uint32_t)((c + 1) & 1) * 9216u * 4u;          \
            const uint32_t ab = sbase + st, wb = sbase + st + 4608u * 4u;      \
            const int kn = (c + 1) << 5;                                       \
            _Pragma("unroll")                                                  \
            for (int i = 0; i < 4; i++) {                                      \
                const int row = r0 + i * 32;                                   \
                const uint32_t off = (uint32_t)(row * 36 + sg * 4) * 4u;       \
                cp16(ab + off, Ag + (size_t)row * K + kn + sg * 4);            \
                cp16(wb + off, Wg + (size_t)row * K + kn + sg * 4);            \
            }                                                                  \
            asm volatile("cp.async.commit_group;" ::: "memory");               \
            asm volatile("cp.async.wait_group 1;" ::: "memory");               \
        } else {                                                               \
            asm volatile("cp.async.wait_group 0;" ::: "memory");               \
        }                                                                      \
        __syncthreads();                                                       \
        const uint32_t* As = sw + (c & 1) * 9216;                              \
        const uint32_t* Ws = As + 4608;                                        \
        _Pragma("unroll")                                                      \
        for (int ks = 0; ks < 4; ks++) {                                       \
            const int k0 = ks * 8;                                             \
            uint32_t af[4][4];                                                 \
            _Pragma("unroll")                                                  \
            for (int mt = 0; mt < 4; mt++) {                                   \
                const int r = wm * 64 + mt * 16 + gid;                         \
                af[mt][0] = As[ r      * 36 + k0 + tig    ];                   \
                af[mt][1] = As[(r + 8) * 36 + k0 + tig    ];                   \
                af[mt][2] = As[ r      * 36 + k0 + tig + 4];                   \
                af[mt][3] = As[(r + 8) * 36 + k0 + tig + 4];                   \
            }                                                                  \
            uint32_t bf[4][2];                                                 \
            _Pragma("unroll")                                                  \
            for (int nt = 0; nt < 4; nt++) {                                   \
                const int n = wn * 32 + nt * 8 + gid;                          \
                bf[nt][0] = Ws[n * 36 + k0 + tig    ];                         \
                bf[nt][1] = Ws[n * 36 + k0 + tig + 4];                         \
            }                                                                  \
            _Pragma("unroll")                                                  \
            for (int mt = 0; mt < 4; mt++)                                     \
                _Pragma("unroll")                                              \
                for (int nt = 0; nt < 4; nt++)                                 \
                    mma_tf32(acc[mt][nt], af[mt], bf[nt]);                     \
        }                                                                      \
        __syncthreads();                                                       \
    }

// ---- fused QKV projection ------------------------------------------------
__global__ __launch_bounds__(256, 2)
void mgemm_qkv(const float* __restrict__ A, const float* __restrict__ Wall,
               const float* __restrict__ bq, const float* __restrict__ bk,
               const float* __restrict__ bv, float* __restrict__ Call, int K)
{
    extern __shared__ uint32_t sw[];
    const uint32_t sbase = smem_u32(sw);
    const int tid  = threadIdx.x;
    const int wid  = tid >> 5;
    const int lane = tid & 31;
    const int gid  = lane >> 2;
    const int tig  = lane & 3;
    const int wm   = wid >> 2;
    const int wn   = wid & 3;
    const int z    = blockIdx.z;

    const float* Ag = A + (size_t)blockIdx.y * 128 * K;
    const float* Wg = Wall + (size_t)z * EMB * EMB + (size_t)blockIdx.x * 128 * K;
    const float* bias = (z == 0) ? bq : (z == 1) ? bk : bv;
    float* C = Call + (size_t)z * HSZ;
    const float scale = (z == 0) ? 0.125f : 1.f;

    GEMM_BODY(Ag, Wg)

    #pragma unroll
    for (int mt = 0; mt < 4; mt++) {
        #pragma unroll
        for (int nt = 0; nt < 4; nt++) {
            const int n = blockIdx.x * 128 + wn * 32 + nt * 8 + tig * 2;
            const float b0 = bias[n], b1 = bias[n + 1];
            #pragma unroll
            for (int half = 0; half < 2; half++) {
                const int m = blockIdx.y * 128 + wm * 64 + mt * 16 + gid + half * 8;
                float2 v;
                v.x = rtf((acc[mt][nt][half * 2 + 0] + b0) * scale);
                v.y = rtf((acc[mt][nt][half * 2 + 1] + b1) * scale);
                const int s = m >> 1, b = m & 1;
                const int h = n >> 6, d = n & 63;
                *(float2*)(C + (((size_t)(b * NH + h)) * S_LEN + s) * HD + d) = v;
            }
        }
    }
}

// ---- output projection ----------------------------------------------------
__global__ __launch_bounds__(256, 2)
void mgemm_out(const float* __restrict__ A, const float* __restrict__ W,
               const float* __restrict__ bias, float* __restrict__ C, int K)
{
    extern __shared__ uint32_t sw[];
    const uint32_t sbase = smem_u32(sw);
    const int tid  = threadIdx.x;
    const int wid  = tid >> 5;
    const int lane = tid & 31;
    const int gid  = lane >> 2;
    const int tig  = lane & 3;
    const int wm   = wid >> 2;
    const int wn   = wid & 3;

    const float* Ag = A + (size_t)blockIdx.y * 128 * K;
    const float* Wg = W + (size_t)blockIdx.x * 128 * K;

    GEMM_BODY(Ag, Wg)

    #pragma unroll
    for (int mt = 0; mt < 4; mt++) {
        #pragma unroll
        for (int nt = 0; nt < 4; nt++) {
            const int n = blockIdx.x * 128 + wn * 32 + nt * 8 + tig * 2;
            const float b0 = bias[n], b1 = bias[n + 1];
            #pragma unroll
            for (int half = 0; half < 2; half++) {
                const int m = blockIdx.y * 128 + wm * 64 + mt * 16 + gid + half * 8;
                float2 v;
                v.x = acc[mt][nt][half * 2 + 0] + b0;
                v.y = acc[mt][nt][half * 2 + 1] + b1;
                *(float2*)(C + (size_t)m * (gridDim.x * 128) + n) = v;
            }
        }
    }
}

// =================== split-tf32 (3xMMA) GEMM + ReLU for the mask MLP =======
__global__ __launch_bounds__(256)
void mgemm_3x_relu(const float* __restrict__ A, const float* __restrict__ W,
                   const float* __restrict__ bias, float* __restrict__ C, int K)
{
    extern __shared__ uint32_t sw[];
    const uint32_t sbase = smem_u32(sw);
    const float* swf = (const float*)sw;
    const int tid  = threadIdx.x;
    const int wid  = tid >> 5;
    const int lane = tid & 31;
    const int gid  = lane >> 2;
    const int tig  = lane & 3;
    const int wm   = wid >> 2;
    const int wn   = wid & 3;

    const float* Ag = A + (size_t)blockIdx.y * 128 * K;
    const float* Wg = W + (size_t)blockIdx.x * 128 * K;

    float acc[4][4][4];
    #pragma unroll
    for (int i = 0; i < 4; i++)
        #pragma unroll
        for (int j = 0; j < 4; j++)
            #pragma unroll
            for (int f = 0; f < 4; f++) acc[i][j][f] = 0.f;

    const int NC = K >> 5;
    const int r0 = tid >> 3;
    const int sg = tid & 7;

    {
        const uint32_t ab = sbase, wb = sbase + 4608u * 4u;
        #pragma unroll
        for (int i = 0; i < 4; i++) {
            const int row = r0 + i * 32;
            const uint32_t off = (uint32_t)(row * 36 + sg * 4) * 4u;
            cp16(ab + off, Ag + (size_t)row * K + sg * 4);
            cp16(wb + off, Wg + (size_t)row * K + sg * 4);
        }
        asm volatile("cp.async.commit_group;" ::: "memory");
    }

    for (int c = 0; c < NC; c++) {
        if (c + 1 < NC) {
            const uint32_t st = (uint32_t)((c + 1) & 1) * 9216u * 4u;
            const uint32_t ab = sbase + st, wb = sbase + st + 4608u * 4u;
            const int kn = (c + 1) << 5;
            #pragma unroll
            for (int i = 0; i < 4; i++) {
                const int row = r0 + i * 32;
                const uint32_t off = (uint32_t)(row * 36 + sg * 4) * 4u;
                cp16(ab + off, Ag + (size_t)row * K + kn + sg * 4);
                cp16(wb + off, Wg + (size_t)row * K + kn + sg * 4);
            }
            asm volatile("cp.async.commit_group;" ::: "memory");
            asm volatile("cp.async.wait_group 1;" ::: "memory");
        } else {
            asm volatile("cp.async.wait_group 0;" ::: "memory");
        }
        __syncthreads();

        const float* As = swf + (c & 1) * 9216;
        const float* Ws = As + 4608;
        #pragma unroll
        for (int ks = 0; ks < 4; ks++) {
            const int k0 = ks * 8;
            uint32_t ah[4][4], al[4][4];
            #pragma unroll
            for (int mt = 0; mt < 4; mt++) {
                const int r = wm * 64 + mt * 16 + gid;
                float a0 = As[ r      * 36 + k0 + tig    ];
                float a1 = As[(r + 8) * 36 + k0 + tig    ];
                float a2 = As[ r      * 36 + k0 + tig + 4];
                float a3 = As[(r + 8) * 36 + k0 + tig + 4];
                ah[mt][0] = f2tf(a0); al[mt][0] = f2tf(a0 - __uint_as_float(ah[mt][0]));
                ah[mt][1] = f2tf(a1); al[mt][1] = f2tf(a1 - __uint_as_float(ah[mt][1]));
                ah[mt][2] = f2tf(a2); al[mt][2] = f2tf(a2 - __uint_as_float(ah[mt][2]));
                ah[mt][3] = f2tf(a3); al[mt][3] = f2tf(a3 - __uint_as_float(ah[mt][3]));
            }
            uint32_t bh_[4][2], bl_[4][2];
            #pragma unroll
            for (int nt = 0; nt < 4; nt++) {
                const int n = wn * 32 + nt * 8 + gid;
                float b0 = Ws[n * 36 + k0 + tig    ];
                float b1 = Ws[n * 36 + k0 + tig + 4];
                bh_[nt][0] = f2tf(b0); bl_[nt][0] = f2tf(b0 - __uint_as_float(bh_[nt][0]));
                bh_[nt][1] = f2tf(b1); bl_[nt][1] = f2tf(b1 - __uint_as_float(bh_[nt][1]));
            }
            #pragma unroll
            for (int mt = 0; mt < 4; mt++)
                #pragma unroll
                for (int nt = 0; nt < 4; nt++) {
                    mma_tf32(acc[mt][nt], al[mt], bh_[nt]);
                    mma_tf32(acc[mt][nt], ah[mt], bl_[nt]);
                    mma_tf32(acc[mt][nt], ah[mt], bh_[nt]);
                }
        }
        __syncthreads();
    }

    #pragma unroll
    for (int mt = 0; mt < 4; mt++) {
        #pragma unroll
        for (int nt = 0; nt < 4; nt++) {
            const int n = blockIdx.x * 128 + wn * 32 + nt * 8 + tig * 2;
            const float b0 = bias[n], b1 = bias[n + 1];
            #pragma unroll
            for (int half = 0; half < 2; half++) {
                const int m = blockIdx.y * 128 + wm * 64 + mt * 16 + gid + half * 8;
                float2 v;
                v.x = fmaxf(acc[mt][nt][half * 2 + 0] + b0, 0.f);
                v.y = fmaxf(acc[mt][nt][half * 2 + 1] + b1, 0.f);
                *(float2*)(C + (size_t)m * (gridDim.x * 128) + n) = v;
            }
        }
    }
}

// =================== tensor-core flash attention (k-permuted) ==============
// 256 threads, 128 Q rows/CTA, 2 CTAs/SM. Within each k=8 block, thread tig
// owns physical k = {2tig, 2tig+1} (same permutation on both operands).
// K tiles stride 72 words (LDS.64 conflict-free); V stride 68 (LDS.32 c-free).
// smem: 2 stages x (K 4608 + V 4352) = 17920 words = 71680 B.
__global__ __launch_bounds__(256, 2)
void flash_tc(const float* __restrict__ Q, const float* __restrict__ Kg,
              const float* __restrict__ Vg, const float* __restrict__ gate,
              float* __restrict__ ctx)
{
    extern __shared__ uint32_t sw[];
    const uint32_t sbase = smem_u32(sw);
    const int tid  = threadIdx.x;
    const int wid  = tid >> 5;
    const int lane = tid & 31;
    const int gid  = lane >> 2;
    const int tig  = lane & 3;
    const int bh   = blockIdx.y;
    const int b    = bh >> 4, h = bh & 15;
    const int q0   = blockIdx.x * 128;

    const float* Qt = Q  + ((size_t)bh * S_LEN + q0) * HD;
    const float* Kb = Kg + (size_t)bh * S_LEN * HD;
    const float* Vb = Vg + (size_t)bh * S_LEN * HD;

    // ---- stage Q (stride 72) then load permuted Q fragments (LDS.64) ------
    #pragma unroll
    for (int i = 0; i < 8; i++) {
        const int fi = tid + i * 256;            // 0..2047 float4s
        const int r = fi >> 4, c4 = (fi & 15) * 4;
        float4 v = *(const float4*)(Qt + r * 64 + c4);
        uint32_t* d = &sw[r * 72 + c4];
        d[0] = __float_as_uint(v.x); d[1] = __float_as_uint(v.y);
        d[2] = __float_as_uint(v.z); d[3] = __float_as_uint(v.w);
    }
    __syncthreads();
    uint32_t qa[8][4];
    {
        const int r0q = wid * 16 + gid;
        #pragma unroll
        for (int ks = 0; ks < 8; ks++) {
            uint2 t0 = *(const uint2*)&sw[ r0q      * 72 + ks * 8 + 2 * tig];
            uint2 t1 = *(const uint2*)&sw[(r0q + 8) * 72 + ks * 8 + 2 * tig];
            qa[ks][0] = t0.x; qa[ks][1] = t1.x;   // k = 2tig   (slot lo)
            qa[ks][2] = t0.y; qa[ks][3] = t1.y;   // k = 2tig+1 (slot hi)
        }
    }
    __syncthreads();

    // ---- issue first two K/V tiles into stages 0,1 -------------------------
    #pragma unroll 1
    for (int t = 0; t < 2; t++) {
        const uint32_t kb = sbase + (uint32_t)t * 8960u * 4u;
        const uint32_t vb = kb + 4608u * 4u;
        const float* Ksrc = Kb + (size_t)t * 64 * 64;
        const float* Vsrc = Vb + (size_t)t * 64 * 64;
        #pragma unroll
        for (int i = 0; i < 4; i++) {
            const int fi = tid + i * 256;        // 0..1023
            const int r = fi >> 4, c4 = (fi & 15) * 4;
            cp16(kb + (uint32_t)(r * 72 + c4) * 4u, Ksrc + r * 64 + c4);
            cp16(vb + (uint32_t)(r * 68 + c4) * 4u, Vsrc + r * 64 + c4);
        }
        asm volatile("cp.async.commit_group;" ::: "memory");
    }

    float miA = -INFINITY, miB = -INFINITY, liA = 0.f, liB = 0.f;
    float oa[8][4];
    #pragma unroll
    for (int nt = 0; nt < 8; nt++)
        #pragma unroll
        for (int f = 0; f < 4; f++) oa[nt][f] = 0.f;

    const int NT = S_LEN / 64;
    for (int t = 0; t < NT; t++) {
        if (t < NT - 2) asm volatile("cp.async.wait_group 1;" ::: "memory");
        else            asm volatile("cp.async.wait_group 0;" ::: "memory");
        __syncthreads();
        const uint32_t* Ks = sw + (t & 1) * 8960;
        const uint32_t* Vs = Ks + 4608;

        // ---- S = Q K^T : B-fragments via one LDS.64 each --------------------
        float sa[8][4];
        #pragma unroll
        for (int nt = 0; nt < 8; nt++)
            #pragma unroll
            for (int f = 0; f < 4; f++) sa[nt][f] = 0.f;
        #pragma unroll
        for (int ks = 0; ks < 8; ks++) {
            #pragma unroll
            for (int nt = 0; nt < 8; nt++) {
                uint2 u = *(const uint2*)&Ks[(nt * 8 + gid) * 72 + ks * 8 + 2 * tig];
                uint32_t bf[2] = { u.x, u.y };
                mma_tf32(sa[nt], qa[ks], bf);
            }
        }

        // ---- online softmax; P converted to tf32 IN PLACE in sa ------------
        float rmA = -INFINITY, rmB = -INFINITY;
        #pragma unroll
        for (int nt = 0; nt < 8; nt++) {
            rmA = fmaxf(rmA, fmaxf(sa[nt][0], sa[nt][1]));
            rmB = fmaxf(rmB, fmaxf(sa[nt][2], sa[nt][3]));
        }
        rmA = fmaxf(rmA, __shfl_xor_sync(0xffffffffu, rmA, 1));
        rmA = fmaxf(rmA, __shfl_xor_sync(0xffffffffu, rmA, 2));
        rmB = fmaxf(rmB, __shfl_xor_sync(0xffffffffu, rmB, 1));
        rmB = fmaxf(rmB, __shfl_xor_sync(0xffffffffu, rmB, 2));

        const float mAn = fmaxf(miA, rmA);
        const float mBn = fmaxf(miB, rmB);
        const float aA  = __expf(miA - mAn);
        const float aB  = __expf(miB - mBn);
        miA = mAn; miB = mBn;

        float rsA = 0.f, rsB = 0.f;
        #pragma unroll
        for (int nt = 0; nt < 8; nt++) {
            const float p0 = __expf(sa[nt][0] - mAn);
            const float p1 = __expf(sa[nt][1] - mAn);
            const float p2 = __expf(sa[nt][2] - mBn);
            const float p3 = __expf(sa[nt][3] - mBn);
            rsA += p0 + p1; rsB += p2 + p3;
            sa[nt][0] = __uint_as_float(f2tf(p0));
            sa[nt][1] = __uint_as_float(f2tf(p1));
            sa[nt][2] = __uint_as_float(f2tf(p2));
            sa[nt][3] = __uint_as_float(f2tf(p3));
        }
        rsA += __shfl_xor_sync(0xffffffffu, rsA, 1);
        rsA += __shfl_xor_sync(0xffffffffu, rsA, 2);
        rsB += __shfl_xor_sync(0xffffffffu, rsB, 1);
        rsB += __shfl_xor_sync(0xffffffffu, rsB, 2);
        liA = liA * aA + rsA;
        liB = liB * aB + rsB;
        #pragma unroll
        for (int nt = 0; nt < 8; nt++) {
            oa[nt][0] *= aA; oa[nt][1] *= aA;
            oa[nt][2] *= aB; oa[nt][3] *= aB;
        }

        // ---- O += P V : accumulator layout == A-fragment layout (no shfl) --
        #pragma unroll
        for (int ks = 0; ks < 8; ks++) {
            uint32_t af[4];
            af[0] = __float_as_uint(sa[ks][0]);   // [row gid,   key 2tig  ]
            af[1] = __float_as_uint(sa[ks][2]);   // [row gid+8, key 2tig  ]
            af[2] = __float_as_uint(sa[ks][1]);   // [row gid,   key 2tig+1]
            af[3] = __float_as_uint(sa[ks][3]);   // [row gid+8, key 2tig+1]
            #pragma unroll
            for (int nt = 0; nt < 8; nt++) {
                uint32_t bf[2];
                bf[0] = Vs[(ks * 8 + 2 * tig    ) * 68 + nt * 8 + gid];
                bf[1] = Vs[(ks * 8 + 2 * tig + 1) * 68 + nt * 8 + gid];
                mma_tf32(oa[nt], af, bf);
            }
        }
        __syncthreads();

        // ---- prefetch tile t+2 into the buffer just freed -------------------
        if (t + 2 < NT) {
            const uint32_t kb = sbase + (uint32_t)(t & 1) * 8960u * 4u;
            const uint32_t vb = kb + 4608u * 4u;
            const float* Ksrc = Kb + (size_t)(t + 2) * 64 * 64;
            const float* Vsrc = Vb + (size_t)(t + 2) * 64 * 64;
            #pragma unroll
            for (int i = 0; i < 4; i++) {
                const int fi = tid + i * 256;
                const int r = fi >> 4, c4 = (fi & 15) * 4;
                cp16(kb + (uint32_t)(r * 72 + c4) * 4u, Ksrc + r * 64 + c4);
                cp16(vb + (uint32_t)(r * 68 + c4) * 4u, Vsrc + r * 64 + c4);
            }
            asm volatile("cp.async.commit_group;" ::: "memory");
        }
    }

    const int sA = q0 + wid * 16 + gid;
    const int sB = sA + 8;
    const float gA = gate[(size_t)bh * S_LEN + sA];
    const float gB = gate[(size_t)bh * S_LEN + sB];
    const float invA = gA / liA;
    const float invB = gB / liB;
    #pragma unroll
    for (int nt = 0; nt < 8; nt++) {
        const int col = h * 64 + nt * 8 + tig * 2;
        float2 va = { rtf(oa[nt][0] * invA), rtf(oa[nt][1] * invA) };
        float2 vb = { rtf(oa[nt][2] * invB), rtf(oa[nt][3] * invB) };
        *(float2*)(ctx + ((size_t)sA * BATCH + b) * EMB + col) = va;
        *(float2*)(ctx + ((size_t)sB * BATCH + b) * EMB + col) = vb;
    }
}

// ---------------- fold head_sig into inf2 ---------------------------------
__global__ void combine_sig(const float* __restrict__ hs,
                            const float* __restrict__ w2,
                            const float* __restrict__ b2,
                            float* __restrict__ mcomb,
                            float* __restrict__ cbias)
{
    const int idx = blockIdx.x * blockDim.x + threadIdx.x;
    if (idx < NH * HID) {
        const int h = idx / HID, k = idx % HID;
        float a = 0.f;
        #pragma unroll
        for (int j = 0; j < 64; j++) a += hs[h*64 + j] * w2[j*HID + k];
        mcomb[idx] = a;
    }
    if (idx < NH) {
        float a = 0.f;
        #pragma unroll
        for (int j = 0; j < 64; j++) a += hs[idx*64 + j] * b2[j];
        cbias[idx] = a;
    }
}

// ---------------- per-row head scores + top-12 threshold mask -------------
__global__ __launch_bounds__(256)
void head_scores(const float* __restrict__ t1, const float* __restrict__ mcomb,
                 const float* __restrict__ cbias, float* __restrict__ mask)
{
    const int warp = (blockIdx.x * blockDim.x + threadIdx.x) >> 5;
    const int lane = threadIdx.x & 31;
    if (warp >= MROWS) return;
    const float* row = t1 + (size_t)warp * HID;

    float acc[NH];
    #pragma unroll
    for (int h = 0; h < NH; h++) acc[h] = 0.f;
    for (int k = lane; k < HID; k += 32) {
        const float a = row[k];
        #pragma unroll
        for (int h = 0; h < NH; h++) acc[h] += a * mcomb[h*HID + k];
    }
    #pragma unroll
    for (int h = 0; h < NH; h++)
        #pragma unroll
        for (int off = 16; off > 0; off >>= 1)
            acc[h] += __shfl_xor_sync(0xffffffffu, acc[h], off);

    if (lane == 0) {
        float sc[NH], tmp[NH];
        #pragma unroll
        for (int h = 0; h < NH; h++) { sc[h] = acc[h] + cbias[h]; tmp[h] = sc[h]; }
        float thr = 0.f;
        for (int it = 0; it < NH - 4; it++) {
            int bi = 0; float bv = tmp[0];
            #pragma unroll
            for (int h = 1; h < NH; h++) if (tmp[h] > bv) { bv = tmp[h]; bi = h; }
            thr = bv; tmp[bi] = -INFINITY;
        }
        const int s = warp >> 1, b = warp & 1;
        #pragma unroll
        for (int h = 0; h < NH; h++)
            mask[((size_t)(b * NH + h)) * S_LEN + s] = (sc[h] >= thr) ? 1.f : 0.f;
    }
}

// ---------------------------------------------------------------------------
extern "C" void kernel_launch(void* const* d_in, const int* in_sizes, int n_in,
                              void* d_out, int out_size)
{
    const float* query   = (const float*)d_in[0];
    const float* q_w     = (const float*)d_in[1];
    const float* q_b     = (const float*)d_in[2];
    const float* k_w     = (const float*)d_in[3];
    const float* k_b     = (const float*)d_in[4];
    const float* v_w     = (const float*)d_in[5];
    const float* v_b     = (const float*)d_in[6];
    const float* out_w   = (const float*)d_in[7];
    const float* out_b   = (const float*)d_in[8];
    const float* inf1_w  = (const float*)d_in[9];
    const float* inf1_b  = (const float*)d_in[10];
    const float* inf2_w  = (const float*)d_in[11];
    const float* inf2_b  = (const float*)d_in[12];
    const float* head_sig= (const float*)d_in[13];
    float* out = (float*)d_out;

    float *pqkv, *pctx, *pt1, *pmc, *pcb, *pmask, *pqr, *pwqkv, *pwo;
    cudaGetSymbolAddress((void**)&pqkv, g_qkv);
    cudaGetSymbolAddress((void**)&pctx, g_ctx);
    cudaGetSymbolAddress((void**)&pt1,  g_t1);
    cudaGetSymbolAddress((void**)&pmc,  g_mcomb);
    cudaGetSymbolAddress((void**)&pcb,  g_cbias);
    cudaGetSymbolAddress((void**)&pmask,g_mask);
    cudaGetSymbolAddress((void**)&pqr,  g_qr);
    cudaGetSymbolAddress((void**)&pwqkv,g_wqkv);
    cudaGetSymbolAddress((void**)&pwo,  g_wo);

    const int GS = 73728;
    cudaFuncSetAttribute(mgemm_qkv, cudaFuncAttributeMaxDynamicSharedMemorySize, GS);
    cudaFuncSetAttribute(mgemm_out, cudaFuncAttributeMaxDynamicSharedMemorySize, GS);
    cudaFuncSetAttribute(mgemm_3x_relu, cudaFuncAttributeMaxDynamicSharedMemorySize, GS);

    // 0) pre-round query + all 4 big weight matrices in ONE launch
    {
        const int total = NQ4 + 4 * NW4;
        round_all<<<(total + 255)/256, 256>>>(query, q_w, k_w, v_w, out_w,
                                              pqr, pwqkv, pwo);
    }

    // 1) fold head_sig into inf2
    combine_sig<<<(NH*HID + 255)/256, 256>>>(head_sig, inf2_w, inf2_b, pmc, pcb);

    // 2) mask MLP: split-tf32 (near-fp32) for top-k stability
    {
        dim3 g(HID/128, MROWS/128);
        mgemm_3x_relu<<<g, 256, GS>>>(query, inf1_w, inf1_b, pt1, EMB);
    }

    // 3) head scores + top-12 mask (one warp per row)
    head_scores<<<MROWS/8, 256>>>(pt1, pmc, pcb, pmask);

    // 4) fused Q,K,V projections -> (B,H,S,D), one launch (grid.z = 3)
    {
        dim3 g(EMB/128, MROWS/128, 3);
        mgemm_qkv<<<g, 256, GS>>>(pqr, pwqkv, q_b, k_b, v_b, pqkv, EMB);
    }

    // 5) flash attention: k-permuted fragments, 2 CTAs/SM
    {
        const int smem = 17920 * (int)sizeof(uint32_t);   // 71680 B
        cudaFuncSetAttribute(flash_tc,
                             cudaFuncAttributeMaxDynamicSharedMemorySize, smem);
        dim3 g(S_LEN/128, BATCH*NH);
        flash_tc<<<g, 256, smem>>>(pqkv, pqkv + HSZ, pqkv + 2*HSZ, pmask, pctx);
    }

    // 6) output projection
    {
        dim3 g(EMB/128, MROWS/128);
        mgemm_out<<<g, 256, GS>>>(pctx, pwo, out_b, out, EMB);
    }
    (void)in_sizes; (void)n_in; (void)out_size;
}

// round 9
// speedup vs baseline: 1.2430x; 1.0865x over previous
#include <cuda_runtime.h>
#include <math.h>
#include <stdint.h>

#define S_LEN 2048
#define BATCH 2
#define EMB   1024
#define NH    16
#define HD    64
#define HID   512
#define MROWS (S_LEN*BATCH)   // 4096
#define HSZ   (BATCH*NH*S_LEN*HD)

// ---------------- scratch (static device globals; no allocation) ----------
__device__ float g_qkv[3*HSZ];               // q|k|v in (B,H,S,D), tf32-rounded
__device__ float g_ctx[MROWS*EMB];           // (S,B,E) tf32-rounded
__device__ float g_t1 [MROWS*HID];
__device__ float g_mcomb[NH*HID];
__device__ float g_cbias[NH];
__device__ float g_mask[BATCH*NH*S_LEN];
__device__ float g_qr [MROWS*EMB];           // tf32-rounded query
__device__ float g_wqkv[3*EMB*EMB];          // tf32-rounded q_w|k_w|v_w
__device__ float g_wo [EMB*EMB];             // tf32-rounded out_w

// =================== helpers ===============================================
__device__ __forceinline__ uint32_t f2tf(float x) {
    uint32_t r; asm("cvt.rna.tf32.f32 %0, %1;" : "=r"(r) : "f"(x)); return r;
}
__device__ __forceinline__ float rtf(float x) { return __uint_as_float(f2tf(x)); }
__device__ __forceinline__ uint32_t smem_u32(const void* p) {
    uint32_t a;
    asm("{ .reg .u64 t; cvta.to.shared.u64 t, %1; cvt.u32.u64 %0, t; }"
        : "=r"(a) : "l"(p));
    return a;
}
__device__ __forceinline__ void cp16(uint32_t saddr, const void* g) {
    asm volatile("cp.async.cg.shared.global [%0], [%1], 16;"
                 :: "r"(saddr), "l"(g) : "memory");
}
__device__ __forceinline__ void mma_tf32(float* d, const uint32_t* a, const uint32_t* b) {
    asm volatile(
        "mma.sync.aligned.m16n8k8.row.col.f32.tf32.tf32.f32 "
        "{%0,%1,%2,%3}, {%4,%5,%6,%7}, {%8,%9}, {%0,%1,%2,%3};"
        : "+f"(d[0]), "+f"(d[1]), "+f"(d[2]), "+f"(d[3])
        : "r"(a[0]), "r"(a[1]), "r"(a[2]), "r"(a[3]), "r"(b[0]), "r"(b[1]));
}

// ---------------- fused tf32 rounding of query + 4 weight matrices --------
#define NQ4 (MROWS*EMB/4)      // 1048576
#define NW4 (EMB*EMB/4)        // 262144 = 1<<18
__global__ void round_all(const float* __restrict__ q,
                          const float* __restrict__ wq,
                          const float* __restrict__ wk,
                          const float* __restrict__ wv,
                          const float* __restrict__ wo,
                          float* __restrict__ dq,
                          float* __restrict__ dwqkv,
                          float* __restrict__ dwo)
{
    const int i = blockIdx.x * blockDim.x + threadIdx.x;
    const float4* src; float4* dst; int off;
    if (i < NQ4) { src = (const float4*)q; dst = (float4*)dq; off = i; }
    else {
        const int j = i - NQ4;
        const int z = j >> 18;
        off = j & (NW4 - 1);
        if      (z == 0) { src = (const float4*)wq; dst = (float4*)dwqkv; }
        else if (z == 1) { src = (const float4*)wk; dst = (float4*)dwqkv + NW4; }
        else if (z == 2) { src = (const float4*)wv; dst = (float4*)dwqkv + 2*NW4; }
        else             { src = (const float4*)wo; dst = (float4*)dwo; }
    }
    float4 v = src[off];
    v.x = rtf(v.x); v.y = rtf(v.y); v.z = rtf(v.z); v.w = rtf(v.w);
    dst[off] = v;
}

// =================== cp.async pipelined tf32 GEMM core =====================
#define GEMM_BODY(Ag, Wg)                                                      \
    float acc[4][4][4];                                                        \
    _Pragma("unroll")                                                          \
    for (int i = 0; i < 4; i++)                                                \
        _Pragma("unroll")                                                      \
        for (int j = 0; j < 4; j++)                                            \
            _Pragma("unroll")                                                  \
            for (int f = 0; f < 4; f++) acc[i][j][f] = 0.f;                    \
    const int NC = K >> 5;                                                     \
    const int r0 = tid >> 3;                                                   \
    const int sg = tid & 7;                                                    \
    {                                                                          \
        const uint32_t ab = sbase, wb = sbase + 4608u * 4u;                    \
        _Pragma("unroll")                                                      \
        for (int i = 0; i < 4; i++) {                                          \
            const int row = r0 + i * 32;                                       \
            const uint32_t off = (uint32_t)(row * 36 + sg * 4) * 4u;           \
            cp16(ab + off, Ag + (size_t)row * K + sg * 4);                     \
            cp16(wb + off, Wg + (size_t)row * K + sg * 4);                     \
        }                                                                      \
        asm volatile("cp.async.commit_group;" ::: "memory");                   \
    }                                                                          \
    for (int c = 0; c < NC; c++) {                                             \
        if (c + 1 < NC) {                                                      \
            const uint32_t st = (uint32_t)((c + 1) & 1) * 9216u * 4u;          \
            const uint32_t ab = sbase + st, wb = sbase + st + 4608u * 4u;      \
            const int kn = (c + 1) << 5;                                       \
            _Pragma("unroll")                                                  \
            for (int i = 0; i < 4; i++) {                                      \
                const int row = r0 + i * 32;                                   \
                const uint32_t off = (uint32_t)(row * 36 + sg * 4) * 4u;       \
                cp16(ab + off, Ag + (size_t)row * K + kn + sg * 4);            \
                cp16(wb + off, Wg + (size_t)row * K + kn + sg * 4);            \
            }                                                                  \
            asm volatile("cp.async.commit_group;" ::: "memory");               \
            asm volatile("cp.async.wait_group 1;" ::: "memory");               \
        } else {                                                               \
            asm volatile("cp.async.wait_group 0;" ::: "memory");               \
        }                                                                      \
        __syncthreads();                                                       \
        const uint32_t* As = sw + (c & 1) * 9216;                              \
        const uint32_t* Ws = As + 4608;                                        \
        _Pragma("unroll")                                                      \
        for (int ks = 0; ks < 4; ks++) {                                       \
            const int k0 = ks * 8;                                             \
            uint32_t af[4][4];                                                 \
            _Pragma("unroll")                                                  \
            for (int mt = 0; mt < 4; mt++) {                                   \
                const int r = wm * 64 + mt * 16 + gid;                         \
                af[mt][0] = As[ r      * 36 + k0 + tig    ];                   \
                af[mt][1] = As[(r + 8) * 36 + k0 + tig    ];                   \
                af[mt][2] = As[ r      * 36 + k0 + tig + 4];                   \
                af[mt][3] = As[(r + 8) * 36 + k0 + tig + 4];                   \
            }                                                                  \
            uint32_t bf[4][2];                                                 \
            _Pragma("unroll")                                                  \
            for (int nt = 0; nt < 4; nt++) {                                   \
                const int n = wn * 32 + nt * 8 + gid;                          \
                bf[nt][0] = Ws[n * 36 + k0 + tig    ];                         \
                bf[nt][1] = Ws[n * 36 + k0 + tig + 4];                         \
            }                                                                  \
            _Pragma("unroll")                                                  \
            for (int mt = 0; mt < 4; mt++)                                     \
                _Pragma("unroll")                                              \
                for (int nt = 0; nt < 4; nt++)                                 \
                    mma_tf32(acc[mt][nt], af[mt], bf[nt]);                     \
        }                                                                      \
        __syncthreads();                                                       \
    }

// ---- fused QKV projection ------------------------------------------------
__global__ __launch_bounds__(256, 2)
void mgemm_qkv(const float* __restrict__ A, const float* __restrict__ Wall,
               const float* __restrict__ bq, const float* __restrict__ bk,
               const float* __restrict__ bv, float* __restrict__ Call, int K)
{
    extern __shared__ uint32_t sw[];
    const uint32_t sbase = smem_u32(sw);
    const int tid  = threadIdx.x;
    const int wid  = tid >> 5;
    const int lane = tid & 31;
    const int gid  = lane >> 2;
    const int tig  = lane & 3;
    const int wm   = wid >> 2;
    const int wn   = wid & 3;
    const int z    = blockIdx.z;

    const float* Ag = A + (size_t)blockIdx.y * 128 * K;
    const float* Wg = Wall + (size_t)z * EMB * EMB + (size_t)blockIdx.x * 128 * K;
    const float* bias = (z == 0) ? bq : (z == 1) ? bk : bv;
    float* C = Call + (size_t)z * HSZ;
    const float scale = (z == 0) ? 0.125f : 1.f;

    GEMM_BODY(Ag, Wg)

    #pragma unroll
    for (int mt = 0; mt < 4; mt++) {
        #pragma unroll
        for (int nt = 0; nt < 4; nt++) {
            const int n = blockIdx.x * 128 + wn * 32 + nt * 8 + tig * 2;
            const float b0 = bias[n], b1 = bias[n + 1];
            #pragma unroll
            for (int half = 0; half < 2; half++) {
                const int m = blockIdx.y * 128 + wm * 64 + mt * 16 + gid + half * 8;
                float2 v;
                v.x = rtf((acc[mt][nt][half * 2 + 0] + b0) * scale);
                v.y = rtf((acc[mt][nt][half * 2 + 1] + b1) * scale);
                const int s = m >> 1, b = m & 1;
                const int h = n >> 6, d = n & 63;
                *(float2*)(C + (((size_t)(b * NH + h)) * S_LEN + s) * HD + d) = v;
            }
        }
    }
}

// ---- output projection ----------------------------------------------------
__global__ __launch_bounds__(256, 2)
void mgemm_out(const float* __restrict__ A, const float* __restrict__ W,
               const float* __restrict__ bias, float* __restrict__ C, int K)
{
    extern __shared__ uint32_t sw[];
    const uint32_t sbase = smem_u32(sw);
    const int tid  = threadIdx.x;
    const int wid  = tid >> 5;
    const int lane = tid & 31;
    const int gid  = lane >> 2;
    const int tig  = lane & 3;
    const int wm   = wid >> 2;
    const int wn   = wid & 3;

    const float* Ag = A + (size_t)blockIdx.y * 128 * K;
    const float* Wg = W + (size_t)blockIdx.x * 128 * K;

    GEMM_BODY(Ag, Wg)

    #pragma unroll
    for (int mt = 0; mt < 4; mt++) {
        #pragma unroll
        for (int nt = 0; nt < 4; nt++) {
            const int n = blockIdx.x * 128 + wn * 32 + nt * 8 + tig * 2;
            const float b0 = bias[n], b1 = bias[n + 1];
            #pragma unroll
            for (int half = 0; half < 2; half++) {
                const int m = blockIdx.y * 128 + wm * 64 + mt * 16 + gid + half * 8;
                float2 v;
                v.x = acc[mt][nt][half * 2 + 0] + b0;
                v.y = acc[mt][nt][half * 2 + 1] + b1;
                *(float2*)(C + (size_t)m * (gridDim.x * 128) + n) = v;
            }
        }
    }
}

// =================== split-tf32 (3xMMA) GEMM + ReLU for the mask MLP =======
__global__ __launch_bounds__(256)
void mgemm_3x_relu(const float* __restrict__ A, const float* __restrict__ W,
                   const float* __restrict__ bias, float* __restrict__ C, int K)
{
    extern __shared__ uint32_t sw[];
    const uint32_t sbase = smem_u32(sw);
    const float* swf = (const float*)sw;
    const int tid  = threadIdx.x;
    const int wid  = tid >> 5;
    const int lane = tid & 31;
    const int gid  = lane >> 2;
    const int tig  = lane & 3;
    const int wm   = wid >> 2;
    const int wn   = wid & 3;

    const float* Ag = A + (size_t)blockIdx.y * 128 * K;
    const float* Wg = W + (size_t)blockIdx.x * 128 * K;

    float acc[4][4][4];
    #pragma unroll
    for (int i = 0; i < 4; i++)
        #pragma unroll
        for (int j = 0; j < 4; j++)
            #pragma unroll
            for (int f = 0; f < 4; f++) acc[i][j][f] = 0.f;

    const int NC = K >> 5;
    const int r0 = tid >> 3;
    const int sg = tid & 7;

    {
        const uint32_t ab = sbase, wb = sbase + 4608u * 4u;
        #pragma unroll
        for (int i = 0; i < 4; i++) {
            const int row = r0 + i * 32;
            const uint32_t off = (uint32_t)(row * 36 + sg * 4) * 4u;
            cp16(ab + off, Ag + (size_t)row * K + sg * 4);
            cp16(wb + off, Wg + (size_t)row * K + sg * 4);
        }
        asm volatile("cp.async.commit_group;" ::: "memory");
    }

    for (int c = 0; c < NC; c++) {
        if (c + 1 < NC) {
            const uint32_t st = (uint32_t)((c + 1) & 1) * 9216u * 4u;
            const uint32_t ab = sbase + st, wb = sbase + st + 4608u * 4u;
            const int kn = (c + 1) << 5;
            #pragma unroll
            for (int i = 0; i < 4; i++) {
                const int row = r0 + i * 32;
                const uint32_t off = (uint32_t)(row * 36 + sg * 4) * 4u;
                cp16(ab + off, Ag + (size_t)row * K + kn + sg * 4);
                cp16(wb + off, Wg + (size_t)row * K + kn + sg * 4);
            }
            asm volatile("cp.async.commit_group;" ::: "memory");
            asm volatile("cp.async.wait_group 1;" ::: "memory");
        } else {
            asm volatile("cp.async.wait_group 0;" ::: "memory");
        }
        __syncthreads();

        const float* As = swf + (c & 1) * 9216;
        const float* Ws = As + 4608;
        #pragma unroll
        for (int ks = 0; ks < 4; ks++) {
            const int k0 = ks * 8;
            uint32_t ah[4][4], al[4][4];
            #pragma unroll
            for (int mt = 0; mt < 4; mt++) {
                const int r = wm * 64 + mt * 16 + gid;
                float a0 = As[ r      * 36 + k0 + tig    ];
                float a1 = As[(r + 8) * 36 + k0 + tig    ];
                float a2 = As[ r      * 36 + k0 + tig + 4];
                float a3 = As[(r + 8) * 36 + k0 + tig + 4];
                ah[mt][0] = f2tf(a0); al[mt][0] = f2tf(a0 - __uint_as_float(ah[mt][0]));
                ah[mt][1] = f2tf(a1); al[mt][1] = f2tf(a1 - __uint_as_float(ah[mt][1]));
                ah[mt][2] = f2tf(a2); al[mt][2] = f2tf(a2 - __uint_as_float(ah[mt][2]));
                ah[mt][3] = f2tf(a3); al[mt][3] = f2tf(a3 - __uint_as_float(ah[mt][3]));
            }
            uint32_t bh_[4][2], bl_[4][2];
            #pragma unroll
            for (int nt = 0; nt < 4; nt++) {
                const int n = wn * 32 + nt * 8 + gid;
                float b0 = Ws[n * 36 + k0 + tig    ];
                float b1 = Ws[n * 36 + k0 + tig + 4];
                bh_[nt][0] = f2tf(b0); bl_[nt][0] = f2tf(b0 - __uint_as_float(bh_[nt][0]));
                bh_[nt][1] = f2tf(b1); bl_[nt][1] = f2tf(b1 - __uint_as_float(bh_[nt][1]));
            }
            #pragma unroll
            for (int mt = 0; mt < 4; mt++)
                #pragma unroll
                for (int nt = 0; nt < 4; nt++) {
                    mma_tf32(acc[mt][nt], al[mt], bh_[nt]);
                    mma_tf32(acc[mt][nt], ah[mt], bl_[nt]);
                    mma_tf32(acc[mt][nt], ah[mt], bh_[nt]);
                }
        }
        __syncthreads();
    }

    #pragma unroll
    for (int mt = 0; mt < 4; mt++) {
        #pragma unroll
        for (int nt = 0; nt < 4; nt++) {
            const int n = blockIdx.x * 128 + wn * 32 + nt * 8 + tig * 2;
            const float b0 = bias[n], b1 = bias[n + 1];
            #pragma unroll
            for (int half = 0; half < 2; half++) {
                const int m = blockIdx.y * 128 + wm * 64 + mt * 16 + gid + half * 8;
                float2 v;
                v.x = fmaxf(acc[mt][nt][half * 2 + 0] + b0, 0.f);
                v.y = fmaxf(acc[mt][nt][half * 2 + 1] + b1, 0.f);
                *(float2*)(C + (size_t)m * (gridDim.x * 128) + n) = v;
            }
        }
    }
}

// =================== tensor-core flash attention (k-permuted) ==============
__global__ __launch_bounds__(256, 2)
void flash_tc(const float* __restrict__ Q, const float* __restrict__ Kg,
              const float* __restrict__ Vg, const float* __restrict__ gate,
              float* __restrict__ ctx)
{
    extern __shared__ uint32_t sw[];
    const uint32_t sbase = smem_u32(sw);
    const int tid  = threadIdx.x;
    const int wid  = tid >> 5;
    const int lane = tid & 31;
    const int gid  = lane >> 2;
    const int tig  = lane & 3;
    const int bh   = blockIdx.y;
    const int b    = bh >> 4, h = bh & 15;
    const int q0   = blockIdx.x * 128;

    const float* Qt = Q  + ((size_t)bh * S_LEN + q0) * HD;
    const float* Kb = Kg + (size_t)bh * S_LEN * HD;
    const float* Vb = Vg + (size_t)bh * S_LEN * HD;

    #pragma unroll
    for (int i = 0; i < 8; i++) {
        const int fi = tid + i * 256;
        const int r = fi >> 4, c4 = (fi & 15) * 4;
        float4 v = *(const float4*)(Qt + r * 64 + c4);
        uint32_t* d = &sw[r * 72 + c4];
        d[0] = __float_as_uint(v.x); d[1] = __float_as_uint(v.y);
        d[2] = __float_as_uint(v.z); d[3] = __float_as_uint(v.w);
    }
    __syncthreads();
    uint32_t qa[8][4];
    {
        const int r0q = wid * 16 + gid;
        #pragma unroll
        for (int ks = 0; ks < 8; ks++) {
            uint2 t0 = *(const uint2*)&sw[ r0q      * 72 + ks * 8 + 2 * tig];
            uint2 t1 = *(const uint2*)&sw[(r0q + 8) * 72 + ks * 8 + 2 * tig];
            qa[ks][0] = t0.x; qa[ks][1] = t1.x;
            qa[ks][2] = t0.y; qa[ks][3] = t1.y;
        }
    }
    __syncthreads();

    #pragma unroll 1
    for (int t = 0; t < 2; t++) {
        const uint32_t kb = sbase + (uint32_t)t * 8960u * 4u;
        const uint32_t vb = kb + 4608u * 4u;
        const float* Ksrc = Kb + (size_t)t * 64 * 64;
        const float* Vsrc = Vb + (size_t)t * 64 * 64;
        #pragma unroll
        for (int i = 0; i < 4; i++) {
            const int fi = tid + i * 256;
            const int r = fi >> 4, c4 = (fi & 15) * 4;
            cp16(kb + (uint32_t)(r * 72 + c4) * 4u, Ksrc + r * 64 + c4);
            cp16(vb + (uint32_t)(r * 68 + c4) * 4u, Vsrc + r * 64 + c4);
        }
        asm volatile("cp.async.commit_group;" ::: "memory");
    }

    float miA = -INFINITY, miB = -INFINITY, liA = 0.f, liB = 0.f;
    float oa[8][4];
    #pragma unroll
    for (int nt = 0; nt < 8; nt++)
        #pragma unroll
        for (int f = 0; f < 4; f++) oa[nt][f] = 0.f;

    const int NT = S_LEN / 64;
    for (int t = 0; t < NT; t++) {
        if (t < NT - 2) asm volatile("cp.async.wait_group 1;" ::: "memory");
        else            asm volatile("cp.async.wait_group 0;" ::: "memory");
        __syncthreads();
        const uint32_t* Ks = sw + (t & 1) * 8960;
        const uint32_t* Vs = Ks + 4608;

        float sa[8][4];
        #pragma unroll
        for (int nt = 0; nt < 8; nt++)
            #pragma unroll
            for (int f = 0; f < 4; f++) sa[nt][f] = 0.f;
        #pragma unroll
        for (int ks = 0; ks < 8; ks++) {
            #pragma unroll
            for (int nt = 0; nt < 8; nt++) {
                uint2 u = *(const uint2*)&Ks[(nt * 8 + gid) * 72 + ks * 8 + 2 * tig];
                uint32_t bf[2] = { u.x, u.y };
                mma_tf32(sa[nt], qa[ks], bf);
            }
        }

        float rmA = -INFINITY, rmB = -INFINITY;
        #pragma unroll
        for (int nt = 0; nt < 8; nt++) {
            rmA = fmaxf(rmA, fmaxf(sa[nt][0], sa[nt][1]));
            rmB = fmaxf(rmB, fmaxf(sa[nt][2], sa[nt][3]));
        }
        rmA = fmaxf(rmA, __shfl_xor_sync(0xffffffffu, rmA, 1));
        rmA = fmaxf(rmA, __shfl_xor_sync(0xffffffffu, rmA, 2));
        rmB = fmaxf(rmB, __shfl_xor_sync(0xffffffffu, rmB, 1));
        rmB = fmaxf(rmB, __shfl_xor_sync(0xffffffffu, rmB, 2));

        const float mAn = fmaxf(miA, rmA);
        const float mBn = fmaxf(miB, rmB);
        const float aA  = __expf(miA - mAn);
        const float aB  = __expf(miB - mBn);
        miA = mAn; miB = mBn;

        float rsA = 0.f, rsB = 0.f;
        #pragma unroll
        for (int nt = 0; nt < 8; nt++) {
            const float p0 = __expf(sa[nt][0] - mAn);
            const float p1 = __expf(sa[nt][1] - mAn);
            const float p2 = __expf(sa[nt][2] - mBn);
            const float p3 = __expf(sa[nt][3] - mBn);
            rsA += p0 + p1; rsB += p2 + p3;
            sa[nt][0] = __uint_as_float(f2tf(p0));
            sa[nt][1] = __uint_as_float(f2tf(p1));
            sa[nt][2] = __uint_as_float(f2tf(p2));
            sa[nt][3] = __uint_as_float(f2tf(p3));
        }
        rsA += __shfl_xor_sync(0xffffffffu, rsA, 1);
        rsA += __shfl_xor_sync(0xffffffffu, rsA, 2);
        rsB += __shfl_xor_sync(0xffffffffu, rsB, 1);
        rsB += __shfl_xor_sync(0xffffffffu, rsB, 2);
        liA = liA * aA + rsA;
        liB = liB * aB + rsB;
        #pragma unroll
        for (int nt = 0; nt < 8; nt++) {
            oa[nt][0] *= aA; oa[nt][1] *= aA;
            oa[nt][2] *= aB; oa[nt][3] *= aB;
        }

        #pragma unroll
        for (int ks = 0; ks < 8; ks++) {
            uint32_t af[4];
            af[0] = __float_as_uint(sa[ks][0]);
            af[1] = __float_as_uint(sa[ks][2]);
            af[2] = __float_as_uint(sa[ks][1]);
            af[3] = __float_as_uint(sa[ks][3]);
            #pragma unroll
            for (int nt = 0; nt < 8; nt++) {
                uint32_t bf[2];
                bf[0] = Vs[(ks * 8 + 2 * tig    ) * 68 + nt * 8 + gid];
                bf[1] = Vs[(ks * 8 + 2 * tig + 1) * 68 + nt * 8 + gid];
                mma_tf32(oa[nt], af, bf);
            }
        }
        __syncthreads();

        if (t + 2 < NT) {
            const uint32_t kb = sbase + (uint32_t)(t & 1) * 8960u * 4u;
            const uint32_t vb = kb + 4608u * 4u;
            const float* Ksrc = Kb + (size_t)(t + 2) * 64 * 64;
            const float* Vsrc = Vb + (size_t)(t + 2) * 64 * 64;
            #pragma unroll
            for (int i = 0; i < 4; i++) {
                const int fi = tid + i * 256;
                const int r = fi >> 4, c4 = (fi & 15) * 4;
                cp16(kb + (uint32_t)(r * 72 + c4) * 4u, Ksrc + r * 64 + c4);
                cp16(vb + (uint32_t)(r * 68 + c4) * 4u, Vsrc + r * 64 + c4);
            }
            asm volatile("cp.async.commit_group;" ::: "memory");
        }
    }

    const int sA = q0 + wid * 16 + gid;
    const int sB = sA + 8;
    const float gA = gate[(size_t)bh * S_LEN + sA];
    const float gB = gate[(size_t)bh * S_LEN + sB];
    const float invA = gA / liA;
    const float invB = gB / liB;
    #pragma unroll
    for (int nt = 0; nt < 8; nt++) {
        const int col = h * 64 + nt * 8 + tig * 2;
        float2 va = { rtf(oa[nt][0] * invA), rtf(oa[nt][1] * invA) };
        float2 vb = { rtf(oa[nt][2] * invB), rtf(oa[nt][3] * invB) };
        *(float2*)(ctx + ((size_t)sA * BATCH + b) * EMB + col) = va;
        *(float2*)(ctx + ((size_t)sB * BATCH + b) * EMB + col) = vb;
    }
}

// ---------------- fold head_sig into inf2 ---------------------------------
__global__ void combine_sig(const float* __restrict__ hs,
                            const float* __restrict__ w2,
                            const float* __restrict__ b2,
                            float* __restrict__ mcomb,
                            float* __restrict__ cbias)
{
    const int idx = blockIdx.x * blockDim.x + threadIdx.x;
    if (idx < NH * HID) {
        const int h = idx / HID, k = idx % HID;
        float a = 0.f;
        #pragma unroll
        for (int j = 0; j < 64; j++) a += hs[h*64 + j] * w2[j*HID + k];
        mcomb[idx] = a;
    }
    if (idx < NH) {
        float a = 0.f;
        #pragma unroll
        for (int j = 0; j < 64; j++) a += hs[idx*64 + j] * b2[j];
        cbias[idx] = a;
    }
}

// ---------------- head scores + top-12 mask (float4 loads) ----------------
// one warp per row; lane covers k = it*128 + lane*4 .. +3 via LDG.128.
__global__ __launch_bounds__(256)
void head_scores(const float* __restrict__ t1, const float* __restrict__ mcomb,
                 const float* __restrict__ cbias, float* __restrict__ mask)
{
    const int warp = (blockIdx.x * blockDim.x + threadIdx.x) >> 5;
    const int lane = threadIdx.x & 31;
    if (warp >= MROWS) return;
    const float4* row4 = (const float4*)(t1 + (size_t)warp * HID);
    const float4* mc4  = (const float4*)mcomb;

    float acc[NH];
    #pragma unroll
    for (int h = 0; h < NH; h++) acc[h] = 0.f;
    #pragma unroll
    for (int it = 0; it < 4; it++) {
        const int k4 = it * 32 + lane;          // float4 index within row
        const float4 a = row4[k4];
        #pragma unroll
        for (int h = 0; h < NH; h++) {
            const float4 m = mc4[h * (HID/4) + k4];
            acc[h] += a.x*m.x + a.y*m.y + a.z*m.z + a.w*m.w;
        }
    }
    #pragma unroll
    for (int h = 0; h < NH; h++)
        #pragma unroll
        for (int off = 16; off > 0; off >>= 1)
            acc[h] += __shfl_xor_sync(0xffffffffu, acc[h], off);

    if (lane == 0) {
        float sc[NH], tmp[NH];
        #pragma unroll
        for (int h = 0; h < NH; h++) { sc[h] = acc[h] + cbias[h]; tmp[h] = sc[h]; }
        float thr = 0.f;
        for (int it = 0; it < NH - 4; it++) {
            int bi = 0; float bv = tmp[0];
            #pragma unroll
            for (int h = 1; h < NH; h++) if (tmp[h] > bv) { bv = tmp[h]; bi = h; }
            thr = bv; tmp[bi] = -INFINITY;
        }
        const int s = warp >> 1, b = warp & 1;
        #pragma unroll
        for (int h = 0; h < NH; h++)
            mask[((size_t)(b * NH + h)) * S_LEN + s] = (sc[h] >= thr) ? 1.f : 0.f;
    }
}

// ---------------------------------------------------------------------------
extern "C" void kernel_launch(void* const* d_in, const int* in_sizes, int n_in,
                              void* d_out, int out_size)
{
    const float* query   = (const float*)d_in[0];
    const float* q_w     = (const float*)d_in[1];
    const float* q_b     = (const float*)d_in[2];
    const float* k_w     = (const float*)d_in[3];
    const float* k_b     = (const float*)d_in[4];
    const float* v_w     = (const float*)d_in[5];
    const float* v_b     = (const float*)d_in[6];
    const float* out_w   = (const float*)d_in[7];
    const float* out_b   = (const float*)d_in[8];
    const float* inf1_w  = (const float*)d_in[9];
    const float* inf1_b  = (const float*)d_in[10];
    const float* inf2_w  = (const float*)d_in[11];
    const float* inf2_b  = (const float*)d_in[12];
    const float* head_sig= (const float*)d_in[13];
    float* out = (float*)d_out;

    float *pqkv, *pctx, *pt1, *pmc, *pcb, *pmask, *pqr, *pwqkv, *pwo;
    cudaGetSymbolAddress((void**)&pqkv, g_qkv);
    cudaGetSymbolAddress((void**)&pctx, g_ctx);
    cudaGetSymbolAddress((void**)&pt1,  g_t1);
    cudaGetSymbolAddress((void**)&pmc,  g_mcomb);
    cudaGetSymbolAddress((void**)&pcb,  g_cbias);
    cudaGetSymbolAddress((void**)&pmask,g_mask);
    cudaGetSymbolAddress((void**)&pqr,  g_qr);
    cudaGetSymbolAddress((void**)&pwqkv,g_wqkv);
    cudaGetSymbolAddress((void**)&pwo,  g_wo);

    const int GS = 73728;
    cudaFuncSetAttribute(mgemm_qkv, cudaFuncAttributeMaxDynamicSharedMemorySize, GS);
    cudaFuncSetAttribute(mgemm_out, cudaFuncAttributeMaxDynamicSharedMemorySize, GS);
    cudaFuncSetAttribute(mgemm_3x_relu, cudaFuncAttributeMaxDynamicSharedMemorySize, GS);
    {
        const int fsmem = 17920 * (int)sizeof(uint32_t);
        cudaFuncSetAttribute(flash_tc,
                             cudaFuncAttributeMaxDynamicSharedMemorySize, fsmem);
    }

    // side stream + fork/join events (created per call; intentionally not
    // destroyed so the captured graph's stream references stay valid — the
    // harness only invokes kernel_launch a couple of times before replay)
    cudaStream_t s2;
    cudaEvent_t eFork, eJoin;
    cudaStreamCreateWithFlags(&s2, cudaStreamNonBlocking);
    cudaEventCreateWithFlags(&eFork, cudaEventDisableTiming);
    cudaEventCreateWithFlags(&eJoin, cudaEventDisableTiming);

    // fork: side stream handles the mask chain (independent of QKV)
    cudaEventRecord(eFork, 0);
    cudaStreamWaitEvent(s2, eFork, 0);

    // --- side stream: combine_sig -> 3x MLP -> head_scores -----------------
    combine_sig<<<(NH*HID + 255)/256, 256, 0, s2>>>(head_sig, inf2_w, inf2_b,
                                                    pmc, pcb);
    {
        dim3 g(HID/128, MROWS/128);
        mgemm_3x_relu<<<g, 256, GS, s2>>>(query, inf1_w, inf1_b, pt1, EMB);
    }
    head_scores<<<MROWS/8, 256, 0, s2>>>(pt1, pmc, pcb, pmask);
    cudaEventRecord(eJoin, s2);

    // --- main stream: round -> QKV ------------------------------------------
    {
        const int total = NQ4 + 4 * NW4;
        round_all<<<(total + 255)/256, 256>>>(query, q_w, k_w, v_w, out_w,
                                              pqr, pwqkv, pwo);
    }
    {
        dim3 g(EMB/128, MROWS/128, 3);
        mgemm_qkv<<<g, 256, GS>>>(pqr, pwqkv, q_b, k_b, v_b, pqkv, EMB);
    }

    // join: flash needs the gate mask from the side stream
    cudaStreamWaitEvent(0, eJoin, 0);

    {
        const int smem = 17920 * (int)sizeof(uint32_t);
        dim3 g(S_LEN/128, BATCH*NH);
        flash_tc<<<g, 256, smem>>>(pqkv, pqkv + HSZ, pqkv + 2*HSZ, pmask, pctx);
    }
    {
        dim3 g(EMB/128, MROWS/128);
        mgemm_out<<<g, 256, GS>>>(pctx, pwo, out_b, out, EMB);
    }
    (void)in_sizes; (void)n_in; (void)out_size;
}

// round 10
// speedup vs baseline: 1.2982x; 1.0444x over previous
#include <cuda_runtime.h>
#include <math.h>
#include <stdint.h>

#define S_LEN 2048
#define BATCH 2
#define EMB   1024
#define NH    16
#define HD    64
#define HID   512
#define MROWS (S_LEN*BATCH)   // 4096
#define HSZ   (BATCH*NH*S_LEN*HD)
#define LOG2E 1.4426950408889634f

// ---------------- scratch (static device globals; no allocation) ----------
__device__ float g_qkv[3*HSZ];               // q|k|v in (B,H,S,D), tf32-rounded
__device__ float g_ctx[MROWS*EMB];           // (S,B,E) tf32-rounded
__device__ float g_t1 [MROWS*HID];
__device__ float g_mcomb[NH*HID];
__device__ float g_cbias[NH];
__device__ float g_mask[BATCH*NH*S_LEN];
__device__ float g_qr [MROWS*EMB];           // tf32-rounded query
__device__ float g_wqkv[3*EMB*EMB];          // tf32-rounded q_w|k_w|v_w
__device__ float g_wo [EMB*EMB];             // tf32-rounded out_w

// =================== helpers ===============================================
__device__ __forceinline__ uint32_t f2tf(float x) {
    uint32_t r; asm("cvt.rna.tf32.f32 %0, %1;" : "=r"(r) : "f"(x)); return r;
}
__device__ __forceinline__ float rtf(float x) { return __uint_as_float(f2tf(x)); }
__device__ __forceinline__ uint32_t smem_u32(const void* p) {
    uint32_t a;
    asm("{ .reg .u64 t; cvta.to.shared.u64 t, %1; cvt.u32.u64 %0, t; }"
        : "=r"(a) : "l"(p));
    return a;
}
__device__ __forceinline__ void cp16(uint32_t saddr, const void* g) {
    asm volatile("cp.async.cg.shared.global [%0], [%1], 16;"
                 :: "r"(saddr), "l"(g) : "memory");
}
__device__ __forceinline__ void mma_tf32(float* d, const uint32_t* a, const uint32_t* b) {
    asm volatile(
        "mma.sync.aligned.m16n8k8.row.col.f32.tf32.tf32.f32 "
        "{%0,%1,%2,%3}, {%4,%5,%6,%7}, {%8,%9}, {%0,%1,%2,%3};"
        : "+f"(d[0]), "+f"(d[1]), "+f"(d[2]), "+f"(d[3])
        : "r"(a[0]), "r"(a[1]), "r"(a[2]), "r"(a[3]), "r"(b[0]), "r"(b[1]));
}

// ---------------- fused tf32 rounding of query + 4 weight matrices --------
#define NQ4 (MROWS*EMB/4)      // 1048576
#define NW4 (EMB*EMB/4)        // 262144 = 1<<18
__global__ void round_all(const float* __restrict__ q,
                          const float* __restrict__ wq,
                          const float* __restrict__ wk,
                          const float* __restrict__ wv,
                          const float* __restrict__ wo,
                          float* __restrict__ dq,
                          float* __restrict__ dwqkv,
                          float* __restrict__ dwo)
{
    const int i = blockIdx.x * blockDim.x + threadIdx.x;
    const float4* src; float4* dst; int off;
    if (i < NQ4) { src = (const float4*)q; dst = (float4*)dq; off = i; }
    else {
        const int j = i - NQ4;
        const int z = j >> 18;
        off = j & (NW4 - 1);
        if      (z == 0) { src = (const float4*)wq; dst = (float4*)dwqkv; }
        else if (z == 1) { src = (const float4*)wk; dst = (float4*)dwqkv + NW4; }
        else if (z == 2) { src = (const float4*)wv; dst = (float4*)dwqkv + 2*NW4; }
        else             { src = (const float4*)wo; dst = (float4*)dwo; }
    }
    float4 v = src[off];
    v.x = rtf(v.x); v.y = rtf(v.y); v.z = rtf(v.z); v.w = rtf(v.w);
    dst[off] = v;
}

// =================== cp.async pipelined tf32 GEMM core (k-permuted) ========
// Row stride 40 words. Within each k=8 block thread tig owns physical
// k={2tig,2tig+1} on BOTH operands (dot product invariant). Fragment loads
// are LDS.64, conflict-free per 16-lane phase (bank = 8*gid + 2*tig mod 32).
// smem stage: A @0 (5120 w), W @5120 (5120 w); stage stride 10240 w.
#define GEMM_BODY(Ag, Wg)                                                      \
    float acc[4][4][4];                                                        \
    _Pragma("unroll")                                                          \
    for (int i = 0; i < 4; i++)                                                \
        _Pragma("unroll")                                                      \
        for (int j = 0; j < 4; j++)                                            \
            _Pragma("unroll")                                                  \
            for (int f = 0; f < 4; f++) acc[i][j][f] = 0.f;                    \
    const int NC = K >> 5;                                                     \
    const int r0 = tid >> 3;                                                   \
    const int sg = tid & 7;                                                    \
    {                                                                          \
        const uint32_t ab = sbase, wb = sbase + 5120u * 4u;                    \
        _Pragma("unroll")                                                      \
        for (int i = 0; i < 4; i++) {                                          \
            const int row = r0 + i * 32;                                       \
            const uint32_t off = (uint32_t)(row * 40 + sg * 4) * 4u;           \
            cp16(ab + off, Ag + (size_t)row * K + sg * 4);                     \
            cp16(wb + off, Wg + (size_t)row * K + sg * 4);                     \
        }                                                                      \
        asm volatile("cp.async.commit_group;" ::: "memory");                   \
    }                                                                          \
    for (int c = 0; c < NC; c++) {                                             \
        if (c + 1 < NC) {                                                      \
            const uint32_t st = (uint32_t)((c + 1) & 1) * 10240u * 4u;         \
            const uint32_t ab = sbase + st, wb = sbase + st + 5120u * 4u;      \
            const int kn = (c + 1) << 5;                                       \
            _Pragma("unroll")                                                  \
            for (int i = 0; i < 4; i++) {                                      \
                const int row = r0 + i * 32;                                   \
                const uint32_t off = (uint32_t)(row * 40 + sg * 4) * 4u;       \
                cp16(ab + off, Ag + (size_t)row * K + kn + sg * 4);            \
                cp16(wb + off, Wg + (size_t)row * K + kn + sg * 4);            \
            }                                                                  \
            asm volatile("cp.async.commit_group;" ::: "memory");               \
            asm volatile("cp.async.wait_group 1;" ::: "memory");               \
        } else {                                                               \
            asm volatile("cp.async.wait_group 0;" ::: "memory");               \
        }                                                                      \
        __syncthreads();                                                       \
        const uint32_t* As = sw + (c & 1) * 10240;                             \
        const uint32_t* Ws = As + 5120;                                        \
        _Pragma("unroll")                                                      \
        for (int ks = 0; ks < 4; ks++) {                                       \
            const int k0 = ks * 8;                                             \
            uint32_t af[4][4];                                                 \
            _Pragma("unroll")                                                  \
            for (int mt = 0; mt < 4; mt++) {                                   \
                const int r = wm * 64 + mt * 16 + gid;                         \
                uint2 a0 = *(const uint2*)&As[ r      * 40 + k0 + 2 * tig];    \
                uint2 a1 = *(const uint2*)&As[(r + 8) * 40 + k0 + 2 * tig];    \
                af[mt][0] = a0.x; af[mt][1] = a1.x;                            \
                af[mt][2] = a0.y; af[mt][3] = a1.y;                            \
            }                                                                  \
            uint32_t bf[4][2];                                                 \
            _Pragma("unroll")                                                  \
            for (int nt = 0; nt < 4; nt++) {                                   \
                const int n = wn * 32 + nt * 8 + gid;                          \
                uint2 w = *(const uint2*)&Ws[n * 40 + k0 + 2 * tig];           \
                bf[nt][0] = w.x; bf[nt][1] = w.y;                              \
            }                                                                  \
            _Pragma("unroll")                                                  \
            for (int mt = 0; mt < 4; mt++)                                     \
                _Pragma("unroll")                                              \
                for (int nt = 0; nt < 4; nt++)                                 \
                    mma_tf32(acc[mt][nt], af[mt], bf[nt]);                     \
        }                                                                      \
        __syncthreads();                                                       \
    }

// ---- fused QKV projection (Q pre-scaled by 0.125*log2e for exp2 softmax) --
__global__ __launch_bounds__(256, 2)
void mgemm_qkv(const float* __restrict__ A, const float* __restrict__ Wall,
               const float* __restrict__ bq, const float* __restrict__ bk,
               const float* __restrict__ bv, float* __restrict__ Call, int K)
{
    extern __shared__ uint32_t sw[];
    const uint32_t sbase = smem_u32(sw);
    const int tid  = threadIdx.x;
    const int wid  = tid >> 5;
    const int lane = tid & 31;
    const int gid  = lane >> 2;
    const int tig  = lane & 3;
    const int wm   = wid >> 2;
    const int wn   = wid & 3;
    const int z    = blockIdx.z;

    const float* Ag = A + (size_t)blockIdx.y * 128 * K;
    const float* Wg = Wall + (size_t)z * EMB * EMB + (size_t)blockIdx.x * 128 * K;
    const float* bias = (z == 0) ? bq : (z == 1) ? bk : bv;
    float* C = Call + (size_t)z * HSZ;
    const float scale = (z == 0) ? 0.125f * LOG2E : 1.f;

    GEMM_BODY(Ag, Wg)

    #pragma unroll
    for (int mt = 0; mt < 4; mt++) {
        #pragma unroll
        for (int nt = 0; nt < 4; nt++) {
            const int n = blockIdx.x * 128 + wn * 32 + nt * 8 + tig * 2;
            const float b0 = bias[n], b1 = bias[n + 1];
            #pragma unroll
            for (int half = 0; half < 2; half++) {
                const int m = blockIdx.y * 128 + wm * 64 + mt * 16 + gid + half * 8;
                float2 v;
                v.x = rtf((acc[mt][nt][half * 2 + 0] + b0) * scale);
                v.y = rtf((acc[mt][nt][half * 2 + 1] + b1) * scale);
                const int s = m >> 1, b = m & 1;
                const int h = n >> 6, d = n & 63;
                *(float2*)(C + (((size_t)(b * NH + h)) * S_LEN + s) * HD + d) = v;
            }
        }
    }
}

// ---- output projection ----------------------------------------------------
__global__ __launch_bounds__(256, 2)
void mgemm_out(const float* __restrict__ A, const float* __restrict__ W,
               const float* __restrict__ bias, float* __restrict__ C, int K)
{
    extern __shared__ uint32_t sw[];
    const uint32_t sbase = smem_u32(sw);
    const int tid  = threadIdx.x;
    const int wid  = tid >> 5;
    const int lane = tid & 31;
    const int gid  = lane >> 2;
    const int tig  = lane & 3;
    const int wm   = wid >> 2;
    const int wn   = wid & 3;

    const float* Ag = A + (size_t)blockIdx.y * 128 * K;
    const float* Wg = W + (size_t)blockIdx.x * 128 * K;

    GEMM_BODY(Ag, Wg)

    #pragma unroll
    for (int mt = 0; mt < 4; mt++) {
        #pragma unroll
        for (int nt = 0; nt < 4; nt++) {
            const int n = blockIdx.x * 128 + wn * 32 + nt * 8 + tig * 2;
            const float b0 = bias[n], b1 = bias[n + 1];
            #pragma unroll
            for (int half = 0; half < 2; half++) {
                const int m = blockIdx.y * 128 + wm * 64 + mt * 16 + gid + half * 8;
                float2 v;
                v.x = acc[mt][nt][half * 2 + 0] + b0;
                v.y = acc[mt][nt][half * 2 + 1] + b1;
                *(float2*)(C + (size_t)m * (gridDim.x * 128) + n) = v;
            }
        }
    }
}

// =================== split-tf32 (3xMMA) GEMM + ReLU for the mask MLP =======
// (unchanged stride-36 layout; runs hidden on the side stream)
__global__ __launch_bounds__(256)
void mgemm_3x_relu(const float* __restrict__ A, const float* __restrict__ W,
                   const float* __restrict__ bias, float* __restrict__ C, int K)
{
    extern __shared__ uint32_t sw[];
    const uint32_t sbase = smem_u32(sw);
    const float* swf = (const float*)sw;
    const int tid  = threadIdx.x;
    const int wid  = tid >> 5;
    const int lane = tid & 31;
    const int gid  = lane >> 2;
    const int tig  = lane & 3;
    const int wm   = wid >> 2;
    const int wn   = wid & 3;

    const float* Ag = A + (size_t)blockIdx.y * 128 * K;
    const float* Wg = W + (size_t)blockIdx.x * 128 * K;

    float acc[4][4][4];
    #pragma unroll
    for (int i = 0; i < 4; i++)
        #pragma unroll
        for (int j = 0; j < 4; j++)
            #pragma unroll
            for (int f = 0; f < 4; f++) acc[i][j][f] = 0.f;

    const int NC = K >> 5;
    const int r0 = tid >> 3;
    const int sg = tid & 7;

    {
        const uint32_t ab = sbase, wb = sbase + 4608u * 4u;
        #pragma unroll
        for (int i = 0; i < 4; i++) {
            const int row = r0 + i * 32;
            const uint32_t off = (uint32_t)(row * 36 + sg * 4) * 4u;
            cp16(ab + off, Ag + (size_t)row * K + sg * 4);
            cp16(wb + off, Wg + (size_t)row * K + sg * 4);
        }
        asm volatile("cp.async.commit_group;" ::: "memory");
    }

    for (int c = 0; c < NC; c++) {
        if (c + 1 < NC) {
            const uint32_t st = (uint32_t)((c + 1) & 1) * 9216u * 4u;
            const uint32_t ab = sbase + st, wb = sbase + st + 4608u * 4u;
            const int kn = (c + 1) << 5;
            #pragma unroll
            for (int i = 0; i < 4; i++) {
                const int row = r0 + i * 32;
                const uint32_t off = (uint32_t)(row * 36 + sg * 4) * 4u;
                cp16(ab + off, Ag + (size_t)row * K + kn + sg * 4);
                cp16(wb + off, Wg + (size_t)row * K + kn + sg * 4);
            }
            asm volatile("cp.async.commit_group;" ::: "memory");
            asm volatile("cp.async.wait_group 1;" ::: "memory");
        } else {
            asm volatile("cp.async.wait_group 0;" ::: "memory");
        }
        __syncthreads();

        const float* As = swf + (c & 1) * 9216;
        const float* Ws = As + 4608;
        #pragma unroll
        for (int ks = 0; ks < 4; ks++) {
            const int k0 = ks * 8;
            uint32_t ah[4][4], al[4][4];
            #pragma unroll
            for (int mt = 0; mt < 4; mt++) {
                const int r = wm * 64 + mt * 16 + gid;
                float a0 = As[ r      * 36 + k0 + tig    ];
                float a1 = As[(r + 8) * 36 + k0 + tig    ];
                float a2 = As[ r      * 36 + k0 + tig + 4];
                float a3 = As[(r + 8) * 36 + k0 + tig + 4];
                ah[mt][0] = f2tf(a0); al[mt][0] = f2tf(a0 - __uint_as_float(ah[mt][0]));
                ah[mt][1] = f2tf(a1); al[mt][1] = f2tf(a1 - __uint_as_float(ah[mt][1]));
                ah[mt][2] = f2tf(a2); al[mt][2] = f2tf(a2 - __uint_as_float(ah[mt][2]));
                ah[mt][3] = f2tf(a3); al[mt][3] = f2tf(a3 - __uint_as_float(ah[mt][3]));
            }
            uint32_t bh_[4][2], bl_[4][2];
            #pragma unroll
            for (int nt = 0; nt < 4; nt++) {
                const int n = wn * 32 + nt * 8 + gid;
                float b0 = Ws[n * 36 + k0 + tig    ];
                float b1 = Ws[n * 36 + k0 + tig + 4];
                bh_[nt][0] = f2tf(b0); bl_[nt][0] = f2tf(b0 - __uint_as_float(bh_[nt][0]));
                bh_[nt][1] = f2tf(b1); bl_[nt][1] = f2tf(b1 - __uint_as_float(bh_[nt][1]));
            }
            #pragma unroll
            for (int mt = 0; mt < 4; mt++)
                #pragma unroll
                for (int nt = 0; nt < 4; nt++) {
                    mma_tf32(acc[mt][nt], al[mt], bh_[nt]);
                    mma_tf32(acc[mt][nt], ah[mt], bl_[nt]);
                    mma_tf32(acc[mt][nt], ah[mt], bh_[nt]);
                }
        }
        __syncthreads();
    }

    #pragma unroll
    for (int mt = 0; mt < 4; mt++) {
        #pragma unroll
        for (int nt = 0; nt < 4; nt++) {
            const int n = blockIdx.x * 128 + wn * 32 + nt * 8 + tig * 2;
            const float b0 = bias[n], b1 = bias[n + 1];
            #pragma unroll
            for (int half = 0; half < 2; half++) {
                const int m = blockIdx.y * 128 + wm * 64 + mt * 16 + gid + half * 8;
                float2 v;
                v.x = fmaxf(acc[mt][nt][half * 2 + 0] + b0, 0.f);
                v.y = fmaxf(acc[mt][nt][half * 2 + 1] + b1, 0.f);
                *(float2*)(C + (size_t)m * (gridDim.x * 128) + n) = v;
            }
        }
    }
}

// =================== tensor-core flash attention (k-permuted, exp2) ========
// S is in log2 domain (Q pre-scaled by 0.125*log2e); softmax uses exp2f.
__global__ __launch_bounds__(256, 2)
void flash_tc(const float* __restrict__ Q, const float* __restrict__ Kg,
              const float* __restrict__ Vg, const float* __restrict__ gate,
              float* __restrict__ ctx)
{
    extern __shared__ uint32_t sw[];
    const uint32_t sbase = smem_u32(sw);
    const int tid  = threadIdx.x;
    const int wid  = tid >> 5;
    const int lane = tid & 31;
    const int gid  = lane >> 2;
    const int tig  = lane & 3;
    const int bh   = blockIdx.y;
    const int b    = bh >> 4, h = bh & 15;
    const int q0   = blockIdx.x * 128;

    const float* Qt = Q  + ((size_t)bh * S_LEN + q0) * HD;
    const float* Kb = Kg + (size_t)bh * S_LEN * HD;
    const float* Vb = Vg + (size_t)bh * S_LEN * HD;

    #pragma unroll
    for (int i = 0; i < 8; i++) {
        const int fi = tid + i * 256;
        const int r = fi >> 4, c4 = (fi & 15) * 4;
        float4 v = *(const float4*)(Qt + r * 64 + c4);
        uint32_t* d = &sw[r * 72 + c4];
        d[0] = __float_as_uint(v.x); d[1] = __float_as_uint(v.y);
        d[2] = __float_as_uint(v.z); d[3] = __float_as_uint(v.w);
    }
    __syncthreads();
    uint32_t qa[8][4];
    {
        const int r0q = wid * 16 + gid;
        #pragma unroll
        for (int ks = 0; ks < 8; ks++) {
            uint2 t0 = *(const uint2*)&sw[ r0q      * 72 + ks * 8 + 2 * tig];
            uint2 t1 = *(const uint2*)&sw[(r0q + 8) * 72 + ks * 8 + 2 * tig];
            qa[ks][0] = t0.x; qa[ks][1] = t1.x;
            qa[ks][2] = t0.y; qa[ks][3] = t1.y;
        }
    }
    __syncthreads();

    #pragma unroll 1
    for (int t = 0; t < 2; t++) {
        const uint32_t kb = sbase + (uint32_t)t * 8960u * 4u;
        const uint32_t vb = kb + 4608u * 4u;
        const float* Ksrc = Kb + (size_t)t * 64 * 64;
        const float* Vsrc = Vb + (size_t)t * 64 * 64;
        #pragma unroll
        for (int i = 0; i < 4; i++) {
            const int fi = tid + i * 256;
            const int r = fi >> 4, c4 = (fi & 15) * 4;
            cp16(kb + (uint32_t)(r * 72 + c4) * 4u, Ksrc + r * 64 + c4);
            cp16(vb + (uint32_t)(r * 68 + c4) * 4u, Vsrc + r * 64 + c4);
        }
        asm volatile("cp.async.commit_group;" ::: "memory");
    }

    float miA = -INFINITY, miB = -INFINITY, liA = 0.f, liB = 0.f;
    float oa[8][4];
    #pragma unroll
    for (int nt = 0; nt < 8; nt++)
        #pragma unroll
        for (int f = 0; f < 4; f++) oa[nt][f] = 0.f;

    const int NT = S_LEN / 64;
    for (int t = 0; t < NT; t++) {
        if (t < NT - 2) asm volatile("cp.async.wait_group 1;" ::: "memory");
        else            asm volatile("cp.async.wait_group 0;" ::: "memory");
        __syncthreads();
        const uint32_t* Ks = sw + (t & 1) * 8960;
        const uint32_t* Vs = Ks + 4608;

        float sa[8][4];
        #pragma unroll
        for (int nt = 0; nt < 8; nt++)
            #pragma unroll
            for (int f = 0; f < 4; f++) sa[nt][f] = 0.f;
        #pragma unroll
        for (int ks = 0; ks < 8; ks++) {
            #pragma unroll
            for (int nt = 0; nt < 8; nt++) {
                uint2 u = *(const uint2*)&Ks[(nt * 8 + gid) * 72 + ks * 8 + 2 * tig];
                uint32_t bf[2] = { u.x, u.y };
                mma_tf32(sa[nt], qa[ks], bf);
            }
        }

        float rmA = -INFINITY, rmB = -INFINITY;
        #pragma unroll
        for (int nt = 0; nt < 8; nt++) {
            rmA = fmaxf(rmA, fmaxf(sa[nt][0], sa[nt][1]));
            rmB = fmaxf(rmB, fmaxf(sa[nt][2], sa[nt][3]));
        }
        rmA = fmaxf(rmA, __shfl_xor_sync(0xffffffffu, rmA, 1));
        rmA = fmaxf(rmA, __shfl_xor_sync(0xffffffffu, rmA, 2));
        rmB = fmaxf(rmB, __shfl_xor_sync(0xffffffffu, rmB, 1));
        rmB = fmaxf(rmB, __shfl_xor_sync(0xffffffffu, rmB, 2));

        const float mAn = fmaxf(miA, rmA);
        const float mBn = fmaxf(miB, rmB);
        const float aA  = exp2f(miA - mAn);
        const float aB  = exp2f(miB - mBn);
        miA = mAn; miB = mBn;

        float rsA = 0.f, rsB = 0.f;
        #pragma unroll
        for (int nt = 0; nt < 8; nt++) {
            const float p0 = exp2f(sa[nt][0] - mAn);
            const float p1 = exp2f(sa[nt][1] - mAn);
            const float p2 = exp2f(sa[nt][2] - mBn);
            const float p3 = exp2f(sa[nt][3] - mBn);
            rsA += p0 + p1; rsB += p2 + p3;
            sa[nt][0] = __uint_as_float(f2tf(p0));
            sa[nt][1] = __uint_as_float(f2tf(p1));
            sa[nt][2] = __uint_as_float(f2tf(p2));
            sa[nt][3] = __uint_as_float(f2tf(p3));
        }
        rsA += __shfl_xor_sync(0xffffffffu, rsA, 1);
        rsA += __shfl_xor_sync(0xffffffffu, rsA, 2);
        rsB += __shfl_xor_sync(0xffffffffu, rsB, 1);
        rsB += __shfl_xor_sync(0xffffffffu, rsB, 2);
        liA = liA * aA + rsA;
        liB = liB * aB + rsB;
        #pragma unroll
        for (int nt = 0; nt < 8; nt++) {
            oa[nt][0] *= aA; oa[nt][1] *= aA;
            oa[nt][2] *= aB; oa[nt][3] *= aB;
        }

        #pragma unroll
        for (int ks = 0; ks < 8; ks++) {
            uint32_t af[4];
            af[0] = __float_as_uint(sa[ks][0]);
            af[1] = __float_as_uint(sa[ks][2]);
            af[2] = __float_as_uint(sa[ks][1]);
            af[3] = __float_as_uint(sa[ks][3]);
            #pragma unroll
            for (int nt = 0; nt < 8; nt++) {
                uint32_t bf[2];
                bf[0] = Vs[(ks * 8 + 2 * tig    ) * 68 + nt * 8 + gid];
                bf[1] = Vs[(ks * 8 + 2 * tig + 1) * 68 + nt * 8 + gid];
                mma_tf32(oa[nt], af, bf);
            }
        }
        __syncthreads();

        if (t + 2 < NT) {
            const uint32_t kb = sbase + (uint32_t)(t & 1) * 8960u * 4u;
            const uint32_t vb = kb + 4608u * 4u;
            const float* Ksrc = Kb + (size_t)(t + 2) * 64 * 64;
            const float* Vsrc = Vb + (size_t)(t + 2) * 64 * 64;
            #pragma unroll
            for (int i = 0; i < 4; i++) {
                const int fi = tid + i * 256;
                const int r = fi >> 4, c4 = (fi & 15) * 4;
                cp16(kb + (uint32_t)(r * 72 + c4) * 4u, Ksrc + r * 64 + c4);
                cp16(vb + (uint32_t)(r * 68 + c4) * 4u, Vsrc + r * 64 + c4);
            }
            asm volatile("cp.async.commit_group;" ::: "memory");
        }
    }

    const int sA = q0 + wid * 16 + gid;
    const int sB = sA + 8;
    const float gA = gate[(size_t)bh * S_LEN + sA];
    const float gB = gate[(size_t)bh * S_LEN + sB];
    const float invA = gA / liA;
    const float invB = gB / liB;
    #pragma unroll
    for (int nt = 0; nt < 8; nt++) {
        const int col = h * 64 + nt * 8 + tig * 2;
        float2 va = { rtf(oa[nt][0] * invA), rtf(oa[nt][1] * invA) };
        float2 vb = { rtf(oa[nt][2] * invB), rtf(oa[nt][3] * invB) };
        *(float2*)(ctx + ((size_t)sA * BATCH + b) * EMB + col) = va;
        *(float2*)(ctx + ((size_t)sB * BATCH + b) * EMB + col) = vb;
    }
}

// ---------------- fold head_sig into inf2 ---------------------------------
__global__ void combine_sig(const float* __restrict__ hs,
                            const float* __restrict__ w2,
                            const float* __restrict__ b2,
                            float* __restrict__ mcomb,
                            float* __restrict__ cbias)
{
    const int idx = blockIdx.x * blockDim.x + threadIdx.x;
    if (idx < NH * HID) {
        const int h = idx / HID, k = idx % HID;
        float a = 0.f;
        #pragma unroll
        for (int j = 0; j < 64; j++) a += hs[h*64 + j] * w2[j*HID + k];
        mcomb[idx] = a;
    }
    if (idx < NH) {
        float a = 0.f;
        #pragma unroll
        for (int j = 0; j < 64; j++) a += hs[idx*64 + j] * b2[j];
        cbias[idx] = a;
    }
}

// ---------------- head scores + top-12 mask (float4 loads) ----------------
__global__ __launch_bounds__(256)
void head_scores(const float* __restrict__ t1, const float* __restrict__ mcomb,
                 const float* __restrict__ cbias, float* __restrict__ mask)
{
    const int warp = (blockIdx.x * blockDim.x + threadIdx.x) >> 5;
    const int lane = threadIdx.x & 31;
    if (warp >= MROWS) return;
    const float4* row4 = (const float4*)(t1 + (size_t)warp * HID);
    const float4* mc4  = (const float4*)mcomb;

    float acc[NH];
    #pragma unroll
    for (int h = 0; h < NH; h++) acc[h] = 0.f;
    #pragma unroll
    for (int it = 0; it < 4; it++) {
        const int k4 = it * 32 + lane;
        const float4 a = row4[k4];
        #pragma unroll
        for (int h = 0; h < NH; h++) {
            const float4 m = mc4[h * (HID/4) + k4];
            acc[h] += a.x*m.x + a.y*m.y + a.z*m.z + a.w*m.w;
        }
    }
    #pragma unroll
    for (int h = 0; h < NH; h++)
        #pragma unroll
        for (int off = 16; off > 0; off >>= 1)
            acc[h] += __shfl_xor_sync(0xffffffffu, acc[h], off);

    if (lane == 0) {
        float sc[NH], tmp[NH];
        #pragma unroll
        for (int h = 0; h < NH; h++) { sc[h] = acc[h] + cbias[h]; tmp[h] = sc[h]; }
        float thr = 0.f;
        for (int it = 0; it < NH - 4; it++) {
            int bi = 0; float bv = tmp[0];
            #pragma unroll
            for (int h = 1; h < NH; h++) if (tmp[h] > bv) { bv = tmp[h]; bi = h; }
            thr = bv; tmp[bi] = -INFINITY;
        }
        const int s = warp >> 1, b = warp & 1;
        #pragma unroll
        for (int h = 0; h < NH; h++)
            mask[((size_t)(b * NH + h)) * S_LEN + s] = (sc[h] >= thr) ? 1.f : 0.f;
    }
}

// ---------------------------------------------------------------------------
extern "C" void kernel_launch(void* const* d_in, const int* in_sizes, int n_in,
                              void* d_out, int out_size)
{
    const float* query   = (const float*)d_in[0];
    const float* q_w     = (const float*)d_in[1];
    const float* q_b     = (const float*)d_in[2];
    const float* k_w     = (const float*)d_in[3];
    const float* k_b     = (const float*)d_in[4];
    const float* v_w     = (const float*)d_in[5];
    const float* v_b     = (const float*)d_in[6];
    const float* out_w   = (const float*)d_in[7];
    const float* out_b   = (const float*)d_in[8];
    const float* inf1_w  = (const float*)d_in[9];
    const float* inf1_b  = (const float*)d_in[10];
    const float* inf2_w  = (const float*)d_in[11];
    const float* inf2_b  = (const float*)d_in[12];
    const float* head_sig= (const float*)d_in[13];
    float* out = (float*)d_out;

    float *pqkv, *pctx, *pt1, *pmc, *pcb, *pmask, *pqr, *pwqkv, *pwo;
    cudaGetSymbolAddress((void**)&pqkv, g_qkv);
    cudaGetSymbolAddress((void**)&pctx, g_ctx);
    cudaGetSymbolAddress((void**)&pt1,  g_t1);
    cudaGetSymbolAddress((void**)&pmc,  g_mcomb);
    cudaGetSymbolAddress((void**)&pcb,  g_cbias);
    cudaGetSymbolAddress((void**)&pmask,g_mask);
    cudaGetSymbolAddress((void**)&pqr,  g_qr);
    cudaGetSymbolAddress((void**)&pwqkv,g_wqkv);
    cudaGetSymbolAddress((void**)&pwo,  g_wo);

    const int GS  = 81920;   // k-permuted GEMM: 2 stages x 10240 words
    const int GS3 = 73728;   // 3x-relu: old stride-36 layout
    cudaFuncSetAttribute(mgemm_qkv, cudaFuncAttributeMaxDynamicSharedMemorySize, GS);
    cudaFuncSetAttribute(mgemm_out, cudaFuncAttributeMaxDynamicSharedMemorySize, GS);
    cudaFuncSetAttribute(mgemm_3x_relu, cudaFuncAttributeMaxDynamicSharedMemorySize, GS3);
    {
        const int fsmem = 17920 * (int)sizeof(uint32_t);
        cudaFuncSetAttribute(flash_tc,
                             cudaFuncAttributeMaxDynamicSharedMemorySize, fsmem);
    }

    // side stream + fork/join events (created per call; never destroyed so
    // the captured graph's references stay valid)
    cudaStream_t s2;
    cudaEvent_t eFork, eJoin;
    cudaStreamCreateWithFlags(&s2, cudaStreamNonBlocking);
    cudaEventCreateWithFlags(&eFork, cudaEventDisableTiming);
    cudaEventCreateWithFlags(&eJoin, cudaEventDisableTiming);

    cudaEventRecord(eFork, 0);
    cudaStreamWaitEvent(s2, eFork, 0);

    // --- side stream: combine_sig -> 3x MLP -> head_scores -----------------
    combine_sig<<<(NH*HID + 255)/256, 256, 0, s2>>>(head_sig, inf2_w, inf2_b,
                                                    pmc, pcb);
    {
        dim3 g(HID/128, MROWS/128);
        mgemm_3x_relu<<<g, 256, GS3, s2>>>(query, inf1_w, inf1_b, pt1, EMB);
    }
    head_scores<<<MROWS/8, 256, 0, s2>>>(pt1, pmc, pcb, pmask);
    cudaEventRecord(eJoin, s2);

    // --- main stream: round -> QKV ------------------------------------------
    {
        const int total = NQ4 + 4 * NW4;
        round_all<<<(total + 255)/256, 256>>>(query, q_w, k_w, v_w, out_w,
                                              pqr, pwqkv, pwo);
    }
    {
        dim3 g(EMB/128, MROWS/128, 3);
        mgemm_qkv<<<g, 256, GS>>>(pqr, pwqkv, q_b, k_b, v_b, pqkv, EMB);
    }

    cudaStreamWaitEvent(0, eJoin, 0);

    {
        const int smem = 17920 * (int)sizeof(uint32_t);
        dim3 g(S_LEN/128, BATCH*NH);
        flash_tc<<<g, 256, smem>>>(pqkv, pqkv + HSZ, pqkv + 2*HSZ, pmask, pctx);
    }
    {
        dim3 g(EMB/128, MROWS/128);
        mgemm_out<<<g, 256, GS>>>(pctx, pwo, out_b, out, EMB);
    }
    (void)in_sizes; (void)n_in; (void)out_size;
}